// round 11
// baseline (speedup 1.0000x reference)
#include <cuda_runtime.h>
#include <math.h>
#include <stdint.h>

#define Bb 8
#define Tt 1024
#define Dd 512
#define Hh 8
#define DHh 64
#define DEPTHL 8
#define FFf 2048
#define NHh 8
#define BSz 64
#define NBk 16
#define NC (NHh*NBk)
#define BHn (Bb*Hh)
#define SEG (NHh*Tt)

// ---------------- scratch ----------------
__device__ float g_x1[Bb*Tt*Dd];
__device__ float g_x2[Bb*Tt*Dd];
__device__ float g_xn[Bb*Tt*Dd];
__device__ float g_qk[Bb*Tt*Dd];
__device__ float g_v [Bb*Tt*Dd];
__device__ float g_ao[Bb*Tt*Dd];
__device__ float g_ffh[Bb*Tt*FFf];
__device__ float g_bo[(size_t)BHn*NHh*Tt*DHh];
__device__ float g_slog[BHn*NHh*Tt];
__device__ int   g_st [BHn*SEG];
__device__ int   g_bkt[BHn*SEG];
__device__ float g_pool[Bb*Dd];

// ---------------- helpers ----------------
__device__ __forceinline__ float gelu_fast(float x) {
    float u = 0.7978845608028654f*(x + 0.044715f*x*x*x);
    float t = 1.f - 2.f/(__expf(2.f*u) + 1.f);
    return 0.5f*x*(1.f + t);
}

__device__ __forceinline__ float blockReduceSum256(float val, float* red) {
    #pragma unroll
    for (int o = 16; o; o >>= 1) val += __shfl_xor_sync(0xffffffffu, val, o);
    int w = threadIdx.x >> 5;
    if ((threadIdx.x & 31) == 0) red[w] = val;
    __syncthreads();
    float r = (threadIdx.x < 8) ? red[threadIdx.x] : 0.f;
    if (threadIdx.x < 32) {
        #pragma unroll
        for (int o = 4; o; o >>= 1) r += __shfl_xor_sync(0xffffffffu, r, o);
        if (threadIdx.x == 0) red[0] = r;
    }
    __syncthreads();
    float out = red[0];
    __syncthreads();
    return out;
}

__device__ __forceinline__ unsigned f2tf32(float x) {
    unsigned r;
    asm("cvt.rna.tf32.f32 %0, %1;" : "=r"(r) : "f"(x));
    return r;
}

__device__ __forceinline__ void mma_tf32(float* c,
    unsigned a0, unsigned a1, unsigned a2, unsigned a3,
    unsigned b0, unsigned b1) {
    asm volatile(
        "mma.sync.aligned.m16n8k8.row.col.f32.tf32.tf32.f32 "
        "{%0,%1,%2,%3}, {%4,%5,%6,%7}, {%8,%9}, {%0,%1,%2,%3};"
        : "+f"(c[0]), "+f"(c[1]), "+f"(c[2]), "+f"(c[3])
        : "r"(a0), "r"(a1), "r"(a2), "r"(a3), "r"(b0), "r"(b1));
}

// ---------------- embedding ----------------
__global__ void embed_kernel(const int* __restrict__ ids,
                             const float* __restrict__ tok,
                             const float* __restrict__ pos,
                             float* __restrict__ x1, float* __restrict__ x2) {
    int i = blockIdx.x*256 + threadIdx.x;
    if (i >= Bb*Tt*Dd) return;
    int d = i & (Dd-1);
    int bt = i >> 9;
    int t = bt & (Tt-1);
    int id = ids[bt];
    if (id < 0) id = 0;
    if (id >= 6400) id = 6399;
    float v = tok[(size_t)id*Dd + d] + pos[t*Dd + d];
    x1[i] = v; x2[i] = v;
}

// ---------------- layernorm ----------------
__global__ void ln_kernel(const float* __restrict__ x, const float* __restrict__ xb,
                          float* __restrict__ y,
                          const float* __restrict__ g, const float* __restrict__ bia) {
    __shared__ float red[8];
    int row = blockIdx.x;
    int i0 = row*Dd + threadIdx.x;
    float v0, v1;
    if (xb) { v0 = 0.5f*(x[i0] + xb[i0]); v1 = 0.5f*(x[i0+256] + xb[i0+256]); }
    else    { v0 = x[i0];                 v1 = x[i0+256]; }
    float s = blockReduceSum256(v0+v1, red);
    float mean = s * (1.f/512.f);
    float d0 = v0 - mean, d1 = v1 - mean;
    float s2 = blockReduceSum256(d0*d0 + d1*d1, red);
    float inv = rsqrtf(s2*(1.f/512.f) + 1e-5f);
    y[i0]     = d0*inv*g[threadIdx.x]     + bia[threadIdx.x];
    y[i0+256] = d1*inv*g[threadIdx.x+256] + bia[threadIdx.x+256];
}

// ---------------- tensor-core GEMM (3xTF32, hi/lo pre-split in smem) ----------------
template<int EPI>
__global__ void __launch_bounds__(256) gemm_kernel(const float* __restrict__ A,
                            const float* __restrict__ Bm,
                            const float* __restrict__ bias, float* __restrict__ C,
                            int M, int N, int K) {
    __shared__ unsigned AsH[16][136], AsL[16][136];
    __shared__ unsigned BsH[16][136], BsL[16][136];
    const int tid  = threadIdx.x;
    const int lane = tid & 31;
    const int warp = tid >> 5;
    const int wm = warp & 1;
    const int wn = warp >> 1;
    const int gid = lane >> 2;
    const int qid = lane & 3;
    const int bm = blockIdx.y*128, bn = blockIdx.x*128;

    float c[4][4][4];
    #pragma unroll
    for (int mt = 0; mt < 4; mt++)
        #pragma unroll
        for (int nt = 0; nt < 4; nt++)
            #pragma unroll
            for (int e = 0; e < 4; e++) c[mt][nt][e] = 0.f;

    const int aR  = (tid + 0)   >> 2, aK  = ((tid + 0)   & 3)*4;
    const int aR2 = (tid + 256) >> 2, aK2 = ((tid + 256) & 3)*4;
    const int bK  = (tid + 0)   >> 5, bN  = ((tid + 0)   & 31)*4;
    const int bK2 = (tid + 256) >> 5, bN2 = ((tid + 256) & 31)*4;

    const int nk = K >> 4;

    #define SPLIT_A(kk, mm, xv) { unsigned hh = f2tf32(xv); \
        AsH[kk][mm] = hh; AsL[kk][mm] = f2tf32((xv) - __uint_as_float(hh)); }
    #define SPLIT_B(kk, nn, xv) { unsigned hh = f2tf32(xv); \
        BsH[kk][nn] = hh; BsL[kk][nn] = f2tf32((xv) - __uint_as_float(hh)); }

    {
        float4 v0 = *(const float4*)(A + (size_t)(bm + aR)*K + aK);
        float4 v1 = *(const float4*)(A + (size_t)(bm + aR2)*K + aK2);
        float4 w0 = *(const float4*)(Bm + (size_t)bK*N  + bn + bN);
        float4 w1 = *(const float4*)(Bm + (size_t)bK2*N + bn + bN2);
        SPLIT_A(aK+0, aR, v0.x); SPLIT_A(aK+1, aR, v0.y);
        SPLIT_A(aK+2, aR, v0.z); SPLIT_A(aK+3, aR, v0.w);
        SPLIT_A(aK2+0, aR2, v1.x); SPLIT_A(aK2+1, aR2, v1.y);
        SPLIT_A(aK2+2, aR2, v1.z); SPLIT_A(aK2+3, aR2, v1.w);
        SPLIT_B(bK, bN+0, w0.x); SPLIT_B(bK, bN+1, w0.y);
        SPLIT_B(bK, bN+2, w0.z); SPLIT_B(bK, bN+3, w0.w);
        SPLIT_B(bK2, bN2+0, w1.x); SPLIT_B(bK2, bN2+1, w1.y);
        SPLIT_B(bK2, bN2+2, w1.z); SPLIT_B(bK2, bN2+3, w1.w);
    }
    __syncthreads();

    for (int kt = 0; kt < nk; kt++) {
        float4 pa0, pa1, pb0, pb1;
        if (kt + 1 < nk) {
            int k0 = (kt + 1)*16;
            pa0 = *(const float4*)(A + (size_t)(bm + aR)*K  + k0 + aK);
            pa1 = *(const float4*)(A + (size_t)(bm + aR2)*K + k0 + aK2);
            pb0 = *(const float4*)(Bm + (size_t)(k0 + bK)*N  + bn + bN);
            pb1 = *(const float4*)(Bm + (size_t)(k0 + bK2)*N + bn + bN2);
        }

        #pragma unroll
        for (int ks = 0; ks < 2; ks++) {
            const int k0 = ks*8;
            unsigned ahi[4][4], alo[4][4];
            #pragma unroll
            for (int mt = 0; mt < 4; mt++) {
                int mc = wm*64 + mt*16;
                ahi[mt][0] = AsH[k0+qid  ][mc+gid];   alo[mt][0] = AsL[k0+qid  ][mc+gid];
                ahi[mt][1] = AsH[k0+qid  ][mc+gid+8]; alo[mt][1] = AsL[k0+qid  ][mc+gid+8];
                ahi[mt][2] = AsH[k0+qid+4][mc+gid];   alo[mt][2] = AsL[k0+qid+4][mc+gid];
                ahi[mt][3] = AsH[k0+qid+4][mc+gid+8]; alo[mt][3] = AsL[k0+qid+4][mc+gid+8];
            }
            #pragma unroll
            for (int nt = 0; nt < 4; nt++) {
                int nc = wn*32 + nt*8;
                unsigned bh0 = BsH[k0+qid  ][nc+gid], bl0 = BsL[k0+qid  ][nc+gid];
                unsigned bh1 = BsH[k0+qid+4][nc+gid], bl1 = BsL[k0+qid+4][nc+gid];
                #pragma unroll
                for (int mt = 0; mt < 4; mt++) {
                    mma_tf32(c[mt][nt], ahi[mt][0],ahi[mt][1],ahi[mt][2],ahi[mt][3], bh0, bh1);
                    mma_tf32(c[mt][nt], ahi[mt][0],ahi[mt][1],ahi[mt][2],ahi[mt][3], bl0, bl1);
                    mma_tf32(c[mt][nt], alo[mt][0],alo[mt][1],alo[mt][2],alo[mt][3], bh0, bh1);
                }
            }
        }
        __syncthreads();
        if (kt + 1 < nk) {
            SPLIT_A(aK+0, aR, pa0.x); SPLIT_A(aK+1, aR, pa0.y);
            SPLIT_A(aK+2, aR, pa0.z); SPLIT_A(aK+3, aR, pa0.w);
            SPLIT_A(aK2+0, aR2, pa1.x); SPLIT_A(aK2+1, aR2, pa1.y);
            SPLIT_A(aK2+2, aR2, pa1.z); SPLIT_A(aK2+3, aR2, pa1.w);
            SPLIT_B(bK, bN+0, pb0.x); SPLIT_B(bK, bN+1, pb0.y);
            SPLIT_B(bK, bN+2, pb0.z); SPLIT_B(bK, bN+3, pb0.w);
            SPLIT_B(bK2, bN2+0, pb1.x); SPLIT_B(bK2, bN2+1, pb1.y);
            SPLIT_B(bK2, bN2+2, pb1.z); SPLIT_B(bK2, bN2+3, pb1.w);
        }
        __syncthreads();
    }

    #pragma unroll
    for (int mt = 0; mt < 4; mt++) {
        #pragma unroll
        for (int nt = 0; nt < 4; nt++) {
            int row = bm + wm*64 + mt*16 + gid;
            int col = bn + wn*32 + nt*8 + qid*2;
            float* p0 = C + (size_t)row*N + col;
            float* p1 = C + (size_t)(row+8)*N + col;
            float v00 = c[mt][nt][0], v01 = c[mt][nt][1];
            float v10 = c[mt][nt][2], v11 = c[mt][nt][3];
            if (EPI == 0) {
                p0[0] = v00; p0[1] = v01; p1[0] = v10; p1[1] = v11;
            } else if (EPI == 1) {
                float b0v = bias[col], b1v = bias[col+1];
                p0[0] = gelu_fast(v00 + b0v); p0[1] = gelu_fast(v01 + b1v);
                p1[0] = gelu_fast(v10 + b0v); p1[1] = gelu_fast(v11 + b1v);
            } else if (EPI == 3) {
                p0[0] += v00; p0[1] += v01; p1[0] += v10; p1[1] += v11;
            } else {
                float b0v = bias[col], b1v = bias[col+1];
                p0[0] += v00 + b0v; p0[1] += v01 + b1v;
                p1[0] += v10 + b0v; p1[1] += v11 + b1v;
            }
        }
    }
    #undef SPLIT_A
    #undef SPLIT_B
}

// ---------------- LSH hashing ----------------
__global__ void hash_kernel(const float* __restrict__ rot,
                            const float* __restrict__ qk, int* __restrict__ bkt) {
    __shared__ float rs[DHh*64];
    int tid = threadIdx.x;
    for (int i = tid; i < DHh*64; i += 256) rs[i] = rot[i];
    __syncthreads();
    int idx = blockIdx.x*256 + tid;
    int t  = idx & (Tt-1);
    int nh = (idx >> 10) & 7;
    int bh = idx >> 13;
    int b = bh >> 3, h = bh & 7;
    const float* qrow = &qk[(size_t)(b*Tt + t)*Dd + h*DHh];
    float rv[8];
    #pragma unroll
    for (int r = 0; r < 8; r++) rv[r] = 0.f;
    #pragma unroll 4
    for (int d4 = 0; d4 < 16; d4++) {
        float4 q4 = *(const float4*)(qrow + d4*4);
        float qv[4] = {q4.x, q4.y, q4.z, q4.w};
        #pragma unroll
        for (int e = 0; e < 4; e++) {
            const float* rp = &rs[(d4*4+e)*64 + nh*8];
            #pragma unroll
            for (int r = 0; r < 8; r++) rv[r] += qv[e]*rp[r];
        }
    }
    int best = 0; float bv = rv[0];
    #pragma unroll
    for (int r = 1; r < 8; r++) if (rv[r] > bv) { bv = rv[r]; best = r; }
    #pragma unroll
    for (int r = 0; r < 8; r++) { float nv = -rv[r]; if (nv > bv) { bv = nv; best = 8 + r; } }
    bkt[(bh*NHh + nh)*Tt + t] = best;
}

// ---------------- stable counting sort ----------------
__global__ void sort_kernel(const int* __restrict__ bkt, int* __restrict__ st) {
    __shared__ int sb[Tt];
    __shared__ int cnt[16];
    __shared__ int off[16];
    int base = blockIdx.x*Tt;
    int tid = threadIdx.x;
    for (int i = tid; i < Tt; i += 512) sb[i] = bkt[base + i];
    __syncthreads();
    int w = tid >> 5, lane = tid & 31;
    int c = 0;
    for (int it = 0; it < 32; it++) {
        unsigned m = __ballot_sync(0xffffffffu, sb[it*32 + lane] == w);
        c += __popc(m);
    }
    if (lane == 0) cnt[w] = c;
    __syncthreads();
    if (tid == 0) {
        int s = 0;
        for (int i = 0; i < 16; i++) { off[i] = s; s += cnt[i]; }
    }
    __syncthreads();
    int p = off[w];
    for (int it = 0; it < 32; it++) {
        int t = it*32 + lane;
        int bb = sb[t];
        unsigned m = __ballot_sync(0xffffffffu, bb == w);
        if (bb == w) {
            int pos = p + __popc(m & ((1u << lane) - 1u));
            st[base + pos] = t;
        }
        p += __popc(m);
    }
}

// ---------------- chunked LSH attention (tensor-core QK^T and PV) ----------------
__global__ void __launch_bounds__(256) attn_kernel(const int* __restrict__ st,
                                                   const float* __restrict__ qk,
                                                   const float* __restrict__ vg,
                                                   float* __restrict__ slog,
                                                   float* __restrict__ bo) {
    extern __shared__ float sm[];
    float* qs   = sm;                   // [64][68]  q tile / V half0
    float* ks   = qs + 64*68;           // [64][68]  K half1 / V half1
    float* sd   = ks + 64*68;           // [64][132] dots -> probs
    float* invs = sd + 64*132;          // [128]
    int*   posK = (int*)(invs + 128);   // [128]

    int n = blockIdx.x, bh = blockIdx.y;
    int b = bh >> 3, h = bh & 7;
    int tid = threadIdx.x;
    int nh = n >> 4;
    int segb = bh*SEG;

    const int lane = tid & 31, warp = tid >> 5;
    const int gid = lane >> 2, qid = lane & 3;

    if (tid < 128) {
        int cc = (tid < 64) ? n : ((n + NC - 1) & (NC-1));
        posK[tid] = st[segb + cc*BSz + (tid & 63)];
    }
    __syncthreads();

    for (int i = tid; i < 64*16; i += 256) {
        int r = i >> 4, c4 = (i & 15)*4;
        float4 a = *(const float4*)&qk[(size_t)(b*Tt + posK[r])*Dd + h*DHh + c4];
        qs[r*68 + c4+0] = a.x; qs[r*68 + c4+1] = a.y;
        qs[r*68 + c4+2] = a.z; qs[r*68 + c4+3] = a.w;
        float4 k2 = *(const float4*)&qk[(size_t)(b*Tt + posK[64+r])*Dd + h*DHh + c4];
        ks[r*68 + c4+0] = k2.x; ks[r*68 + c4+1] = k2.y;
        ks[r*68 + c4+2] = k2.z; ks[r*68 + c4+3] = k2.w;
    }
    __syncthreads();

    if (tid < 128) {
        const float* kb = (tid < 64) ? qs : ks;
        int r = tid & 63;
        float s = 0.f;
        #pragma unroll 8
        for (int d = 0; d < 64; d++) { float x = kb[r*68 + d]; s += x*x; }
        invs[tid] = 1.f/(sqrtf(s) + 1e-8f);
    }
    __syncthreads();

    // ---- QK^T via 3xTF32 mma: warp = (mt 0..3, key-half 0..1) ----
    {
        const int mt = warp & 3;
        const int kh = warp >> 2;
        const float* kb = kh ? ks : qs;
        const int r0 = mt*16 + gid;
        float c[8][4];
        #pragma unroll
        for (int nt = 0; nt < 8; nt++)
            #pragma unroll
            for (int e = 0; e < 4; e++) c[nt][e] = 0.f;

        #pragma unroll
        for (int k0 = 0; k0 < 64; k0 += 8) {
            float x0 = qs[r0*68 + k0+qid];
            float x1 = qs[(r0+8)*68 + k0+qid];
            float x2 = qs[r0*68 + k0+qid+4];
            float x3 = qs[(r0+8)*68 + k0+qid+4];
            unsigned ah0 = f2tf32(x0), al0 = f2tf32(x0 - __uint_as_float(ah0));
            unsigned ah1 = f2tf32(x1), al1 = f2tf32(x1 - __uint_as_float(ah1));
            unsigned ah2 = f2tf32(x2), al2 = f2tf32(x2 - __uint_as_float(ah2));
            unsigned ah3 = f2tf32(x3), al3 = f2tf32(x3 - __uint_as_float(ah3));
            #pragma unroll
            for (int nt = 0; nt < 8; nt++) {
                float y0 = kb[(nt*8+gid)*68 + k0+qid];
                float y1 = kb[(nt*8+gid)*68 + k0+qid+4];
                unsigned bh0 = f2tf32(y0), bl0 = f2tf32(y0 - __uint_as_float(bh0));
                unsigned bh1 = f2tf32(y1), bl1 = f2tf32(y1 - __uint_as_float(bh1));
                mma_tf32(c[nt], ah0,ah1,ah2,ah3, bh0, bh1);
                mma_tf32(c[nt], ah0,ah1,ah2,ah3, bl0, bl1);
                mma_tf32(c[nt], al0,al1,al2,al3, bh0, bh1);
            }
        }
        int pq0 = posK[r0], pq1 = posK[r0+8];
        #pragma unroll
        for (int nt = 0; nt < 8; nt++) {
            int kl = nt*8 + qid*2;
            int col = kh*64 + kl;
            float is0 = invs[col]*0.125f, is1 = invs[col+1]*0.125f;
            int pk0 = posK[col], pk1 = posK[col+1];
            float s00 = c[nt][0]*is0; if (pq0 == pk0) s00 = -5e4f;
            float s01 = c[nt][1]*is1; if (pq0 == pk1) s01 = -5e4f;
            float s10 = c[nt][2]*is0; if (pq1 == pk0) s10 = -5e4f;
            float s11 = c[nt][3]*is1; if (pq1 == pk1) s11 = -5e4f;
            sd[r0*132 + col]     = s00; sd[r0*132 + col+1]     = s01;
            sd[(r0+8)*132 + col] = s10; sd[(r0+8)*132 + col+1] = s11;
        }
    }
    __syncthreads();

    // ---- softmax per row ----
    {
        int r = tid >> 2, c4 = tid & 3;
        float vals[32];
        float mx = -1e30f;
        #pragma unroll
        for (int i = 0; i < 32; i++) { vals[i] = sd[r*132 + i*4 + c4]; mx = fmaxf(mx, vals[i]); }
        mx = fmaxf(mx, __shfl_xor_sync(0xffffffffu, mx, 1));
        mx = fmaxf(mx, __shfl_xor_sync(0xffffffffu, mx, 2));
        float se = 0.f;
        #pragma unroll
        for (int i = 0; i < 32; i++) { vals[i] = __expf(vals[i] - mx); se += vals[i]; }
        se += __shfl_xor_sync(0xffffffffu, se, 1);
        se += __shfl_xor_sync(0xffffffffu, se, 2);
        if (c4 == 0) slog[((size_t)bh*NHh + nh)*Tt + posK[r]] = mx + __logf(se);
        float inv_se = 1.f/se;
        #pragma unroll
        for (int i = 0; i < 32; i++) sd[r*132 + i*4 + c4] = vals[i]*inv_se;
    }
    __syncthreads();

    // ---- load V halves over q/k buffers ----
    for (int i = tid; i < 64*16; i += 256) {
        int r = i >> 4, c4 = (i & 15)*4;
        float4 a = *(const float4*)&vg[(size_t)(b*Tt + posK[r])*Dd + h*DHh + c4];
        qs[r*68 + c4+0] = a.x; qs[r*68 + c4+1] = a.y;
        qs[r*68 + c4+2] = a.z; qs[r*68 + c4+3] = a.w;
        float4 k2 = *(const float4*)&vg[(size_t)(b*Tt + posK[64+r])*Dd + h*DHh + c4];
        ks[r*68 + c4+0] = k2.x; ks[r*68 + c4+1] = k2.y;
        ks[r*68 + c4+2] = k2.z; ks[r*68 + c4+3] = k2.w;
    }
    __syncthreads();

    // ---- PV via 3xTF32 mma: warp = (mt 0..3, d-half 0..1) ----
    {
        const int mt = warp & 3;
        const int dh = warp >> 2;
        const int r0 = mt*16 + gid;
        float c[4][4];
        #pragma unroll
        for (int nt = 0; nt < 4; nt++)
            #pragma unroll
            for (int e = 0; e < 4; e++) c[nt][e] = 0.f;

        #pragma unroll
        for (int k0 = 0; k0 < 128; k0 += 8) {
            const float* vb = (k0 < 64) ? qs : ks;
            const int kk = k0 & 63;
            float x0 = sd[r0*132 + k0+qid];
            float x1 = sd[(r0+8)*132 + k0+qid];
            float x2 = sd[r0*132 + k0+qid+4];
            float x3 = sd[(r0+8)*132 + k0+qid+4];
            unsigned ah0 = f2tf32(x0), al0 = f2tf32(x0 - __uint_as_float(ah0));
            unsigned ah1 = f2tf32(x1), al1 = f2tf32(x1 - __uint_as_float(ah1));
            unsigned ah2 = f2tf32(x2), al2 = f2tf32(x2 - __uint_as_float(ah2));
            unsigned ah3 = f2tf32(x3), al3 = f2tf32(x3 - __uint_as_float(ah3));
            #pragma unroll
            for (int nt = 0; nt < 4; nt++) {
                int d = dh*32 + nt*8 + gid;
                float y0 = vb[(kk+qid)*68 + d];
                float y1 = vb[(kk+qid+4)*68 + d];
                unsigned bh0 = f2tf32(y0), bl0 = f2tf32(y0 - __uint_as_float(bh0));
                unsigned bh1 = f2tf32(y1), bl1 = f2tf32(y1 - __uint_as_float(bh1));
                mma_tf32(c[nt], ah0,ah1,ah2,ah3, bh0, bh1);
                mma_tf32(c[nt], ah0,ah1,ah2,ah3, bl0, bl1);
                mma_tf32(c[nt], al0,al1,al2,al3, bh0, bh1);
            }
        }
        size_t base0 = ((size_t)bh*NHh + nh)*Tt;
        float* bo0 = &bo[(base0 + posK[r0])*DHh];
        float* bo1 = &bo[(base0 + posK[r0+8])*DHh];
        #pragma unroll
        for (int nt = 0; nt < 4; nt++) {
            int col = dh*32 + nt*8 + qid*2;
            bo0[col] = c[nt][0]; bo0[col+1] = c[nt][1];
            bo1[col] = c[nt][2]; bo1[col+1] = c[nt][3];
        }
    }
}

// ---------------- combine ----------------
__global__ void combine_kernel(const float* __restrict__ slog,
                               const float* __restrict__ bo,
                               float* __restrict__ ao) {
    int idx = blockIdx.x*256 + threadIdx.x;
    if (idx >= BHn*Tt*16) return;
    int d4 = (idx & 15)*4;
    int t  = (idx >> 4) & (Tt-1);
    int bh = idx >> 14;
    float lg[NHh];
    float mx = -1e30f;
    #pragma unroll
    for (int i = 0; i < NHh; i++) {
        lg[i] = slog[((size_t)bh*NHh + i)*Tt + t];
        mx = fmaxf(mx, lg[i]);
    }
    float se = 0.f;
    #pragma unroll
    for (int i = 0; i < NHh; i++) { lg[i] = __expf(lg[i] - mx); se += lg[i]; }
    float inv = 1.f/se;
    float4 out = make_float4(0.f, 0.f, 0.f, 0.f);
    #pragma unroll
    for (int i = 0; i < NHh; i++) {
        float w = lg[i]*inv;
        float4 bv = *(const float4*)&bo[(((size_t)bh*NHh + i)*Tt + t)*DHh + d4];
        out.x += w*bv.x; out.y += w*bv.y; out.z += w*bv.z; out.w += w*bv.w;
    }
    int b = bh >> 3, h = bh & 7;
    *(float4*)&ao[(size_t)(b*Tt + t)*Dd + h*DHh + d4] = out;
}

// ---------------- pooling + fc ----------------
__global__ void pool_kernel(const float* __restrict__ xn, float* __restrict__ pool) {
    int b = blockIdx.x, d = threadIdx.x;
    float s = 0.f;
    for (int t = 0; t < Tt; t++) s += xn[(size_t)(b*Tt + t)*Dd + d];
    pool[b*Dd + d] = s * (1.f/(float)Tt);
}

__global__ void fc_kernel(const float* __restrict__ pool,
                          const float* __restrict__ Wfc, float* __restrict__ out) {
    int b = blockIdx.x, n = threadIdx.x;
    float s = 0.f;
    for (int kk = 0; kk < Dd; kk++) s += pool[b*Dd + kk]*Wfc[kk*Dd + n];
    out[b*Dd + n] = s;
}

// ---------------- orchestration ----------------
extern "C" void kernel_launch(void* const* d_in, const int* in_sizes, int n_in,
                              void* d_out, int out_size) {
    const int*   ids = (const int*)  d_in[0];
    const float* tok = (const float*)d_in[1];
    const float* pos = (const float*)d_in[2];
    const float* lag = (const float*)d_in[3];
    const float* lab = (const float*)d_in[4];
    const float* Wqk = (const float*)d_in[5];
    const float* Wv  = (const float*)d_in[6];
    const float* Wo  = (const float*)d_in[7];
    const float* lfg = (const float*)d_in[8];
    const float* lfb = (const float*)d_in[9];
    const float* W1  = (const float*)d_in[10];
    const float* b1  = (const float*)d_in[11];
    const float* W2  = (const float*)d_in[12];
    const float* b2  = (const float*)d_in[13];
    const float* lng = (const float*)d_in[14];
    const float* lnb = (const float*)d_in[15];
    const float* Wfc = (const float*)d_in[16];
    const float* rot = (const float*)d_in[17];
    float* out = (float*)d_out;

    float *x1, *x2, *xn, *qk, *v, *ao, *ffh, *bo, *slog, *pool;
    int *st, *bkt;
    cudaGetSymbolAddress((void**)&x1,   g_x1);
    cudaGetSymbolAddress((void**)&x2,   g_x2);
    cudaGetSymbolAddress((void**)&xn,   g_xn);
    cudaGetSymbolAddress((void**)&qk,   g_qk);
    cudaGetSymbolAddress((void**)&v,    g_v);
    cudaGetSymbolAddress((void**)&ao,   g_ao);
    cudaGetSymbolAddress((void**)&ffh,  g_ffh);
    cudaGetSymbolAddress((void**)&bo,   g_bo);
    cudaGetSymbolAddress((void**)&slog, g_slog);
    cudaGetSymbolAddress((void**)&pool, g_pool);
    cudaGetSymbolAddress((void**)&st,   g_st);
    cudaGetSymbolAddress((void**)&bkt,  g_bkt);

    const int ATTN_SMEM = (64*68*2 + 64*132 + 128)*4 + 128*4;
    cudaFuncSetAttribute(attn_kernel, cudaFuncAttributeMaxDynamicSharedMemorySize, ATTN_SMEM);

    const int M = Bb*Tt;

    embed_kernel<<<(Bb*Tt*Dd + 255)/256, 256>>>(ids, tok, pos, x1, x2);

    for (int l = 0; l < DEPTHL; l++) {
        const float* Wqk_l = Wqk + (size_t)l*Dd*Dd;
        const float* Wv_l  = Wv  + (size_t)l*Dd*Dd;
        const float* Wo_l  = Wo  + (size_t)l*Dd*Dd;
        const float* W1_l  = W1  + (size_t)l*Dd*FFf;
        const float* W2_l  = W2  + (size_t)l*FFf*Dd;
        const float* b1_l  = b1  + (size_t)l*FFf;
        const float* b2_l  = b2  + (size_t)l*Dd;
        const float* rot_l = rot + (size_t)l*DHh*64;

        // attention block: x1 += attn(LN(x2)) @ Wo
        ln_kernel<<<M, 256>>>(x2, nullptr, xn, lag + l*Dd, lab + l*Dd);
        gemm_kernel<0><<<dim3(Dd/128, M/128), 256>>>(xn, Wqk_l, nullptr, qk, M, Dd, Dd);
        gemm_kernel<0><<<dim3(Dd/128, M/128), 256>>>(xn, Wv_l,  nullptr, v,  M, Dd, Dd);
        hash_kernel<<<(BHn*NHh*Tt)/256, 256>>>(rot_l, qk, bkt);
        sort_kernel<<<BHn*NHh, 512>>>(bkt, st);
        attn_kernel<<<dim3(NC, BHn), 256, ATTN_SMEM>>>(st, qk, v, slog, bo);
        combine_kernel<<<(BHn*Tt*16)/256, 256>>>(slog, bo, ao);
        gemm_kernel<3><<<dim3(Dd/128, M/128), 256>>>(ao, Wo_l, nullptr, x1, M, Dd, Dd);

        // feed-forward block: x2 += gelu(LN(x1)@W1 + b1) @ W2 + b2
        ln_kernel<<<M, 256>>>(x1, nullptr, xn, lfg + l*Dd, lfb + l*Dd);
        gemm_kernel<1><<<dim3(FFf/128, M/128), 256>>>(xn, W1_l, b1_l, ffh, M, FFf, Dd);
        gemm_kernel<4><<<dim3(Dd/128, M/128), 256>>>(ffh, W2_l, b2_l, x2, M, Dd, FFf);
    }

    // final: 0.5*(x1+x2) -> LN -> mean over T -> @ Wfc
    ln_kernel<<<M, 256>>>(x1, x2, xn, lng, lnb);
    pool_kernel<<<Bb, Dd>>>(xn, pool);
    fc_kernel<<<Bb, Dd>>>(pool, Wfc, out);
}

// round 12
// speedup vs baseline: 1.0893x; 1.0893x over previous
#include <cuda_runtime.h>
#include <math.h>
#include <stdint.h>

#define Bb 8
#define Tt 1024
#define Dd 512
#define Hh 8
#define DHh 64
#define DEPTHL 8
#define FFf 2048
#define NHh 8
#define BSz 64
#define NBk 16
#define NC (NHh*NBk)
#define BHn (Bb*Hh)
#define SEG (NHh*Tt)

// ---------------- scratch ----------------
__device__ float g_x1[Bb*Tt*Dd];
__device__ float g_x2[Bb*Tt*Dd];
__device__ float g_xn[Bb*Tt*Dd];
__device__ float g_qk[Bb*Tt*Dd];
__device__ float g_v [Bb*Tt*Dd];
__device__ float g_ao[Bb*Tt*Dd];
__device__ float g_ffh[Bb*Tt*FFf];
__device__ float g_bo[(size_t)BHn*NHh*Tt*DHh];
__device__ float g_slog[BHn*NHh*Tt];
__device__ int   g_st [BHn*SEG];
__device__ int   g_bkt[BHn*SEG];
__device__ float g_pool[Bb*Dd];

// ---------------- helpers ----------------
__device__ __forceinline__ float gelu_fast(float x) {
    float u = 0.7978845608028654f*(x + 0.044715f*x*x*x);
    float t = 1.f - 2.f/(__expf(2.f*u) + 1.f);
    return 0.5f*x*(1.f + t);
}

__device__ __forceinline__ float blockReduceSum256(float val, float* red) {
    #pragma unroll
    for (int o = 16; o; o >>= 1) val += __shfl_xor_sync(0xffffffffu, val, o);
    int w = threadIdx.x >> 5;
    if ((threadIdx.x & 31) == 0) red[w] = val;
    __syncthreads();
    float r = (threadIdx.x < 8) ? red[threadIdx.x] : 0.f;
    if (threadIdx.x < 32) {
        #pragma unroll
        for (int o = 4; o; o >>= 1) r += __shfl_xor_sync(0xffffffffu, r, o);
        if (threadIdx.x == 0) red[0] = r;
    }
    __syncthreads();
    float out = red[0];
    __syncthreads();
    return out;
}

__device__ __forceinline__ unsigned f2tf32(float x) {
    unsigned r;
    asm("cvt.rna.tf32.f32 %0, %1;" : "=r"(r) : "f"(x));
    return r;
}

__device__ __forceinline__ void mma_tf32(float* c,
    unsigned a0, unsigned a1, unsigned a2, unsigned a3,
    unsigned b0, unsigned b1) {
    asm volatile(
        "mma.sync.aligned.m16n8k8.row.col.f32.tf32.tf32.f32 "
        "{%0,%1,%2,%3}, {%4,%5,%6,%7}, {%8,%9}, {%0,%1,%2,%3};"
        : "+f"(c[0]), "+f"(c[1]), "+f"(c[2]), "+f"(c[3])
        : "r"(a0), "r"(a1), "r"(a2), "r"(a3), "r"(b0), "r"(b1));
}

__device__ __forceinline__ void cp16(void* smem, const void* gmem) {
    unsigned s = (unsigned)__cvta_generic_to_shared(smem);
    asm volatile("cp.async.ca.shared.global [%0], [%1], 16;" :: "r"(s), "l"(gmem));
}

// ---------------- embedding ----------------
__global__ void embed_kernel(const int* __restrict__ ids,
                             const float* __restrict__ tok,
                             const float* __restrict__ pos,
                             float* __restrict__ x1, float* __restrict__ x2) {
    int i = blockIdx.x*256 + threadIdx.x;
    if (i >= Bb*Tt*Dd) return;
    int d = i & (Dd-1);
    int bt = i >> 9;
    int t = bt & (Tt-1);
    int id = ids[bt];
    if (id < 0) id = 0;
    if (id >= 6400) id = 6399;
    float v = tok[(size_t)id*Dd + d] + pos[t*Dd + d];
    x1[i] = v; x2[i] = v;
}

// ---------------- layernorm ----------------
__global__ void ln_kernel(const float* __restrict__ x, const float* __restrict__ xb,
                          float* __restrict__ y,
                          const float* __restrict__ g, const float* __restrict__ bia) {
    __shared__ float red[8];
    int row = blockIdx.x;
    int i0 = row*Dd + threadIdx.x;
    float v0, v1;
    if (xb) { v0 = 0.5f*(x[i0] + xb[i0]); v1 = 0.5f*(x[i0+256] + xb[i0+256]); }
    else    { v0 = x[i0];                 v1 = x[i0+256]; }
    float s = blockReduceSum256(v0+v1, red);
    float mean = s * (1.f/512.f);
    float d0 = v0 - mean, d1 = v1 - mean;
    float s2 = blockReduceSum256(d0*d0 + d1*d1, red);
    float inv = rsqrtf(s2*(1.f/512.f) + 1e-5f);
    y[i0]     = d0*inv*g[threadIdx.x]     + bia[threadIdx.x];
    y[i0+256] = d1*inv*g[threadIdx.x+256] + bia[threadIdx.x+256];
}

// ---------------- tensor-core GEMM (3xTF32, cp.async double-buffered) ----------------
// logical C = A[MxNl] ; optional fused second output (Bm2/C2, split at nHalf).
// EPI: 0 = store, 1 = gelu(acc+bias) store, 3 = C += acc, 4 = C += acc + bias
template<int EPI>
__global__ void __launch_bounds__(256) gemm_kernel(const float* __restrict__ A,
                            const float* __restrict__ Bm,
                            const float* __restrict__ bias, float* __restrict__ C,
                            int M, int K,
                            const float* __restrict__ Bm2, float* __restrict__ C2,
                            int nHalf, int Nplain) {
    __shared__ float As[2][128][20];
    __shared__ float Bs[2][16][136];

    const int tid  = threadIdx.x;
    const int lane = tid & 31;
    const int warp = tid >> 5;
    const int wm = warp & 1;
    const int wn = warp >> 1;
    const int gid = lane >> 2;
    const int qid = lane & 3;
    const int bm = blockIdx.y*128;

    // fused-output resolution
    const float* Bu = Bm;
    float* Cu = C;
    int bn = blockIdx.x*128;
    int Nld = Nplain;
    if (Bm2 != nullptr) {
        Nld = nHalf;
        if (bn >= nHalf) { Bu = Bm2; Cu = C2; bn -= nHalf; }
    }

    float c[4][4][4];
    #pragma unroll
    for (int mt = 0; mt < 4; mt++)
        #pragma unroll
        for (int nt = 0; nt < 4; nt++)
            #pragma unroll
            for (int e = 0; e < 4; e++) c[mt][nt][e] = 0.f;

    // async copy coordinates: A chunks (512): m=c>>2, ko=(c&3)*4; B chunks (512): k=c>>5, no=(c&31)*4
    const int aM  = (tid + 0)   >> 2, aO  = ((tid + 0)   & 3)*4;
    const int aM2 = (tid + 256) >> 2, aO2 = ((tid + 256) & 3)*4;
    const int bKk  = (tid + 0)   >> 5, bNo  = ((tid + 0)   & 31)*4;
    const int bKk2 = (tid + 256) >> 5, bNo2 = ((tid + 256) & 31)*4;

    const int nk = K >> 4;

    // preload stage 0
    {
        cp16(&As[0][aM ][aO ], A + (size_t)(bm + aM )*K + aO );
        cp16(&As[0][aM2][aO2], A + (size_t)(bm + aM2)*K + aO2);
        cp16(&Bs[0][bKk ][bNo ], Bu + (size_t)bKk *Nld + bn + bNo );
        cp16(&Bs[0][bKk2][bNo2], Bu + (size_t)bKk2*Nld + bn + bNo2);
        asm volatile("cp.async.commit_group;");
        asm volatile("cp.async.wait_group 0;");
    }
    __syncthreads();

    for (int kt = 0; kt < nk; kt++) {
        const int cur = kt & 1;
        if (kt + 1 < nk) {
            const int nxt = cur ^ 1;
            int k0 = (kt + 1)*16;
            cp16(&As[nxt][aM ][aO ], A + (size_t)(bm + aM )*K + k0 + aO );
            cp16(&As[nxt][aM2][aO2], A + (size_t)(bm + aM2)*K + k0 + aO2);
            cp16(&Bs[nxt][bKk ][bNo ], Bu + (size_t)(k0 + bKk )*Nld + bn + bNo );
            cp16(&Bs[nxt][bKk2][bNo2], Bu + (size_t)(k0 + bKk2)*Nld + bn + bNo2);
            asm volatile("cp.async.commit_group;");
        }

        #pragma unroll
        for (int ks = 0; ks < 2; ks++) {
            const int k8 = ks*8;
            unsigned ahi[4][4], alo[4][4];
            #pragma unroll
            for (int mt = 0; mt < 4; mt++) {
                int mc = wm*64 + mt*16;
                float x0 = As[cur][mc+gid  ][k8+qid];
                float x1 = As[cur][mc+gid+8][k8+qid];
                float x2 = As[cur][mc+gid  ][k8+qid+4];
                float x3 = As[cur][mc+gid+8][k8+qid+4];
                ahi[mt][0] = f2tf32(x0); alo[mt][0] = f2tf32(x0 - __uint_as_float(ahi[mt][0]));
                ahi[mt][1] = f2tf32(x1); alo[mt][1] = f2tf32(x1 - __uint_as_float(ahi[mt][1]));
                ahi[mt][2] = f2tf32(x2); alo[mt][2] = f2tf32(x2 - __uint_as_float(ahi[mt][2]));
                ahi[mt][3] = f2tf32(x3); alo[mt][3] = f2tf32(x3 - __uint_as_float(ahi[mt][3]));
            }
            #pragma unroll
            for (int nt = 0; nt < 4; nt++) {
                int nc = wn*32 + nt*8;
                float y0 = Bs[cur][k8+qid  ][nc+gid];
                float y1 = Bs[cur][k8+qid+4][nc+gid];
                unsigned bh0 = f2tf32(y0), bl0 = f2tf32(y0 - __uint_as_float(bh0));
                unsigned bh1 = f2tf32(y1), bl1 = f2tf32(y1 - __uint_as_float(bh1));
                #pragma unroll
                for (int mt = 0; mt < 4; mt++) {
                    mma_tf32(c[mt][nt], ahi[mt][0],ahi[mt][1],ahi[mt][2],ahi[mt][3], bh0, bh1);
                    mma_tf32(c[mt][nt], ahi[mt][0],ahi[mt][1],ahi[mt][2],ahi[mt][3], bl0, bl1);
                    mma_tf32(c[mt][nt], alo[mt][0],alo[mt][1],alo[mt][2],alo[mt][3], bh0, bh1);
                }
            }
        }
        asm volatile("cp.async.wait_group 0;");
        __syncthreads();
    }

    #pragma unroll
    for (int mt = 0; mt < 4; mt++) {
        #pragma unroll
        for (int nt = 0; nt < 4; nt++) {
            int row = bm + wm*64 + mt*16 + gid;
            int col = bn + wn*32 + nt*8 + qid*2;
            float* p0 = Cu + (size_t)row*Nld + col;
            float* p1 = Cu + (size_t)(row+8)*Nld + col;
            float v00 = c[mt][nt][0], v01 = c[mt][nt][1];
            float v10 = c[mt][nt][2], v11 = c[mt][nt][3];
            if (EPI == 0) {
                p0[0] = v00; p0[1] = v01; p1[0] = v10; p1[1] = v11;
            } else if (EPI == 1) {
                float b0v = bias[col], b1v = bias[col+1];
                p0[0] = gelu_fast(v00 + b0v); p0[1] = gelu_fast(v01 + b1v);
                p1[0] = gelu_fast(v10 + b0v); p1[1] = gelu_fast(v11 + b1v);
            } else if (EPI == 3) {
                p0[0] += v00; p0[1] += v01; p1[0] += v10; p1[1] += v11;
            } else {
                float b0v = bias[col], b1v = bias[col+1];
                p0[0] += v00 + b0v; p0[1] += v01 + b1v;
                p1[0] += v10 + b0v; p1[1] += v11 + b1v;
            }
        }
    }
}

// ---------------- LSH hashing ----------------
__global__ void hash_kernel(const float* __restrict__ rot,
                            const float* __restrict__ qk, int* __restrict__ bkt) {
    __shared__ float rs[DHh*64];
    int tid = threadIdx.x;
    for (int i = tid; i < DHh*64; i += 256) rs[i] = rot[i];
    __syncthreads();
    int idx = blockIdx.x*256 + tid;
    int t  = idx & (Tt-1);
    int nh = (idx >> 10) & 7;
    int bh = idx >> 13;
    int b = bh >> 3, h = bh & 7;
    const float* qrow = &qk[(size_t)(b*Tt + t)*Dd + h*DHh];
    float rv[8];
    #pragma unroll
    for (int r = 0; r < 8; r++) rv[r] = 0.f;
    #pragma unroll 4
    for (int d4 = 0; d4 < 16; d4++) {
        float4 q4 = *(const float4*)(qrow + d4*4);
        float qv[4] = {q4.x, q4.y, q4.z, q4.w};
        #pragma unroll
        for (int e = 0; e < 4; e++) {
            const float* rp = &rs[(d4*4+e)*64 + nh*8];
            #pragma unroll
            for (int r = 0; r < 8; r++) rv[r] += qv[e]*rp[r];
        }
    }
    int best = 0; float bv = rv[0];
    #pragma unroll
    for (int r = 1; r < 8; r++) if (rv[r] > bv) { bv = rv[r]; best = r; }
    #pragma unroll
    for (int r = 0; r < 8; r++) { float nv = -rv[r]; if (nv > bv) { bv = nv; best = 8 + r; } }
    bkt[(bh*NHh + nh)*Tt + t] = best;
}

// ---------------- stable counting sort ----------------
__global__ void sort_kernel(const int* __restrict__ bkt, int* __restrict__ st) {
    __shared__ int sb[Tt];
    __shared__ int cnt[16];
    __shared__ int off[16];
    int base = blockIdx.x*Tt;
    int tid = threadIdx.x;
    for (int i = tid; i < Tt; i += 512) sb[i] = bkt[base + i];
    __syncthreads();
    int w = tid >> 5, lane = tid & 31;
    int c = 0;
    for (int it = 0; it < 32; it++) {
        unsigned m = __ballot_sync(0xffffffffu, sb[it*32 + lane] == w);
        c += __popc(m);
    }
    if (lane == 0) cnt[w] = c;
    __syncthreads();
    if (tid == 0) {
        int s = 0;
        for (int i = 0; i < 16; i++) { off[i] = s; s += cnt[i]; }
    }
    __syncthreads();
    int p = off[w];
    for (int it = 0; it < 32; it++) {
        int t = it*32 + lane;
        int bb = sb[t];
        unsigned m = __ballot_sync(0xffffffffu, bb == w);
        if (bb == w) {
            int pos = p + __popc(m & ((1u << lane) - 1u));
            st[base + pos] = t;
        }
        p += __popc(m);
    }
}

// ---------------- chunked LSH attention (R10 fp32 register-tiled) ----------------
__global__ void __launch_bounds__(256) attn_kernel(const int* __restrict__ st,
                                                   const float* __restrict__ qk,
                                                   const float* __restrict__ vg,
                                                   float* __restrict__ slog,
                                                   float* __restrict__ bo) {
    extern __shared__ float sm[];
    float* qs   = sm;
    float* ks   = qs + 64*65;
    float* sd   = ks + 64*65;
    float* invs = sd + 64*132;
    int*   posK = (int*)(invs + 128);

    int n = blockIdx.x, bh = blockIdx.y;
    int b = bh >> 3, h = bh & 7;
    int tid = threadIdx.x;
    int nh = n >> 4;
    int segb = bh*SEG;

    if (tid < 128) {
        int cc = (tid < 64) ? n : ((n + NC - 1) & (NC-1));
        posK[tid] = st[segb + cc*BSz + (tid & 63)];
    }
    __syncthreads();

    for (int i = tid; i < 64*16; i += 256) {
        int r = i >> 4, c4 = (i & 15)*4;
        float4 a = *(const float4*)&qk[(size_t)(b*Tt + posK[r])*Dd + h*DHh + c4];
        qs[r*65 + c4+0] = a.x; qs[r*65 + c4+1] = a.y;
        qs[r*65 + c4+2] = a.z; qs[r*65 + c4+3] = a.w;
        float4 k2 = *(const float4*)&qk[(size_t)(b*Tt + posK[64+r])*Dd + h*DHh + c4];
        ks[r*65 + c4+0] = k2.x; ks[r*65 + c4+1] = k2.y;
        ks[r*65 + c4+2] = k2.z; ks[r*65 + c4+3] = k2.w;
    }
    __syncthreads();

    if (tid < 128) {
        const float* kb = (tid < 64) ? qs : ks;
        int r = tid & 63;
        float s = 0.f;
        #pragma unroll 8
        for (int d = 0; d < 64; d++) { float x = kb[r*65 + d]; s += x*x; }
        invs[tid] = 1.f/(sqrtf(s) + 1e-8f);
    }
    __syncthreads();

    {
        int ty = tid >> 4, tx = tid & 15;
        #pragma unroll
        for (int half = 0; half < 2; half++) {
            const float* kb = half ? ks : qs;
            float acc[4][4];
            #pragma unroll
            for (int i = 0; i < 4; i++)
                #pragma unroll
                for (int j = 0; j < 4; j++) acc[i][j] = 0.f;
            #pragma unroll 4
            for (int d = 0; d < 64; d++) {
                float a0 = qs[(ty*4+0)*65 + d], a1 = qs[(ty*4+1)*65 + d];
                float a2 = qs[(ty*4+2)*65 + d], a3 = qs[(ty*4+3)*65 + d];
                float b0 = kb[(tx*4+0)*65 + d], b1 = kb[(tx*4+1)*65 + d];
                float b2 = kb[(tx*4+2)*65 + d], b3 = kb[(tx*4+3)*65 + d];
                acc[0][0]+=a0*b0; acc[0][1]+=a0*b1; acc[0][2]+=a0*b2; acc[0][3]+=a0*b3;
                acc[1][0]+=a1*b0; acc[1][1]+=a1*b1; acc[1][2]+=a1*b2; acc[1][3]+=a1*b3;
                acc[2][0]+=a2*b0; acc[2][1]+=a2*b1; acc[2][2]+=a2*b2; acc[2][3]+=a2*b3;
                acc[3][0]+=a3*b0; acc[3][1]+=a3*b1; acc[3][2]+=a3*b2; acc[3][3]+=a3*b3;
            }
            #pragma unroll
            for (int i = 0; i < 4; i++) {
                int qr = ty*4 + i, pq = posK[qr];
                #pragma unroll
                for (int j = 0; j < 4; j++) {
                    int kl = tx*4 + j;
                    float s = acc[i][j]*0.125f*invs[half*64 + kl];
                    if (pq == posK[half*64 + kl]) s = -5e4f;
                    sd[qr*132 + half*64 + kl] = s;
                }
            }
        }
    }
    __syncthreads();

    {
        int r = tid >> 2, c4 = tid & 3;
        float vals[32];
        float mx = -1e30f;
        #pragma unroll
        for (int i = 0; i < 32; i++) { vals[i] = sd[r*132 + i*4 + c4]; mx = fmaxf(mx, vals[i]); }
        mx = fmaxf(mx, __shfl_xor_sync(0xffffffffu, mx, 1));
        mx = fmaxf(mx, __shfl_xor_sync(0xffffffffu, mx, 2));
        float se = 0.f;
        #pragma unroll
        for (int i = 0; i < 32; i++) { vals[i] = __expf(vals[i] - mx); se += vals[i]; }
        se += __shfl_xor_sync(0xffffffffu, se, 1);
        se += __shfl_xor_sync(0xffffffffu, se, 2);
        if (c4 == 0) slog[((size_t)bh*NHh + nh)*Tt + posK[r]] = mx + __logf(se);
        float inv_se = 1.f/se;
        #pragma unroll
        for (int i = 0; i < 32; i++) sd[r*132 + i*4 + c4] = vals[i]*inv_se;
    }
    __syncthreads();

    for (int i = tid; i < 64*16; i += 256) {
        int r = i >> 4, c4 = (i & 15)*4;
        float4 a = *(const float4*)&vg[(size_t)(b*Tt + posK[r])*Dd + h*DHh + c4];
        qs[r*65 + c4+0] = a.x; qs[r*65 + c4+1] = a.y;
        qs[r*65 + c4+2] = a.z; qs[r*65 + c4+3] = a.w;
        float4 k2 = *(const float4*)&vg[(size_t)(b*Tt + posK[64+r])*Dd + h*DHh + c4];
        ks[r*65 + c4+0] = k2.x; ks[r*65 + c4+1] = k2.y;
        ks[r*65 + c4+2] = k2.z; ks[r*65 + c4+3] = k2.w;
    }
    __syncthreads();

    {
        int ty = tid >> 4, tx = tid & 15;
        float acc[4][4];
        #pragma unroll
        for (int i = 0; i < 4; i++)
            #pragma unroll
            for (int j = 0; j < 4; j++) acc[i][j] = 0.f;
        #pragma unroll 4
        for (int k = 0; k < 64; k++) {
            float p0 = sd[(ty*4+0)*132 + k], p1 = sd[(ty*4+1)*132 + k];
            float p2 = sd[(ty*4+2)*132 + k], p3 = sd[(ty*4+3)*132 + k];
            float v0 = qs[k*65 + tx*4+0], v1 = qs[k*65 + tx*4+1];
            float v2 = qs[k*65 + tx*4+2], v3 = qs[k*65 + tx*4+3];
            acc[0][0]+=p0*v0; acc[0][1]+=p0*v1; acc[0][2]+=p0*v2; acc[0][3]+=p0*v3;
            acc[1][0]+=p1*v0; acc[1][1]+=p1*v1; acc[1][2]+=p1*v2; acc[1][3]+=p1*v3;
            acc[2][0]+=p2*v0; acc[2][1]+=p2*v1; acc[2][2]+=p2*v2; acc[2][3]+=p2*v3;
            acc[3][0]+=p3*v0; acc[3][1]+=p3*v1; acc[3][2]+=p3*v2; acc[3][3]+=p3*v3;
        }
        #pragma unroll 4
        for (int k = 0; k < 64; k++) {
            float p0 = sd[(ty*4+0)*132 + 64+k], p1 = sd[(ty*4+1)*132 + 64+k];
            float p2 = sd[(ty*4+2)*132 + 64+k], p3 = sd[(ty*4+3)*132 + 64+k];
            float v0 = ks[k*65 + tx*4+0], v1 = ks[k*65 + tx*4+1];
            float v2 = ks[k*65 + tx*4+2], v3 = ks[k*65 + tx*4+3];
            acc[0][0]+=p0*v0; acc[0][1]+=p0*v1; acc[0][2]+=p0*v2; acc[0][3]+=p0*v3;
            acc[1][0]+=p1*v0; acc[1][1]+=p1*v1; acc[1][2]+=p1*v2; acc[1][3]+=p1*v3;
            acc[2][0]+=p2*v0; acc[2][1]+=p2*v1; acc[2][2]+=p2*v2; acc[2][3]+=p2*v3;
            acc[3][0]+=p3*v0; acc[3][1]+=p3*v1; acc[3][2]+=p3*v2; acc[3][3]+=p3*v3;
        }
        #pragma unroll
        for (int i = 0; i < 4; i++) {
            int qr = ty*4 + i;
            float* bop = &bo[(((size_t)bh*NHh + nh)*Tt + posK[qr])*DHh + tx*4];
            *(float4*)bop = make_float4(acc[i][0], acc[i][1], acc[i][2], acc[i][3]);
        }
    }
}

// ---------------- combine ----------------
__global__ void combine_kernel(const float* __restrict__ slog,
                               const float* __restrict__ bo,
                               float* __restrict__ ao) {
    int idx = blockIdx.x*256 + threadIdx.x;
    if (idx >= BHn*Tt*16) return;
    int d4 = (idx & 15)*4;
    int t  = (idx >> 4) & (Tt-1);
    int bh = idx >> 14;
    float lg[NHh];
    float mx = -1e30f;
    #pragma unroll
    for (int i = 0; i < NHh; i++) {
        lg[i] = slog[((size_t)bh*NHh + i)*Tt + t];
        mx = fmaxf(mx, lg[i]);
    }
    float se = 0.f;
    #pragma unroll
    for (int i = 0; i < NHh; i++) { lg[i] = __expf(lg[i] - mx); se += lg[i]; }
    float inv = 1.f/se;
    float4 out = make_float4(0.f, 0.f, 0.f, 0.f);
    #pragma unroll
    for (int i = 0; i < NHh; i++) {
        float w = lg[i]*inv;
        float4 bv = *(const float4*)&bo[(((size_t)bh*NHh + i)*Tt + t)*DHh + d4];
        out.x += w*bv.x; out.y += w*bv.y; out.z += w*bv.z; out.w += w*bv.w;
    }
    int b = bh >> 3, h = bh & 7;
    *(float4*)&ao[(size_t)(b*Tt + t)*Dd + h*DHh + d4] = out;
}

// ---------------- pooling + fc ----------------
__global__ void pool_kernel(const float* __restrict__ xn, float* __restrict__ pool) {
    int b = blockIdx.x, d = threadIdx.x;
    float s = 0.f;
    for (int t = 0; t < Tt; t++) s += xn[(size_t)(b*Tt + t)*Dd + d];
    pool[b*Dd + d] = s * (1.f/(float)Tt);
}

__global__ void fc_kernel(const float* __restrict__ pool,
                          const float* __restrict__ Wfc, float* __restrict__ out) {
    int b = blockIdx.x, n = threadIdx.x;
    float s = 0.f;
    for (int kk = 0; kk < Dd; kk++) s += pool[b*Dd + kk]*Wfc[kk*Dd + n];
    out[b*Dd + n] = s;
}

// ---------------- orchestration ----------------
extern "C" void kernel_launch(void* const* d_in, const int* in_sizes, int n_in,
                              void* d_out, int out_size) {
    const int*   ids = (const int*)  d_in[0];
    const float* tok = (const float*)d_in[1];
    const float* pos = (const float*)d_in[2];
    const float* lag = (const float*)d_in[3];
    const float* lab = (const float*)d_in[4];
    const float* Wqk = (const float*)d_in[5];
    const float* Wv  = (const float*)d_in[6];
    const float* Wo  = (const float*)d_in[7];
    const float* lfg = (const float*)d_in[8];
    const float* lfb = (const float*)d_in[9];
    const float* W1  = (const float*)d_in[10];
    const float* b1  = (const float*)d_in[11];
    const float* W2  = (const float*)d_in[12];
    const float* b2  = (const float*)d_in[13];
    const float* lng = (const float*)d_in[14];
    const float* lnb = (const float*)d_in[15];
    const float* Wfc = (const float*)d_in[16];
    const float* rot = (const float*)d_in[17];
    float* out = (float*)d_out;

    float *x1, *x2, *xn, *qk, *v, *ao, *ffh, *bo, *slog, *pool;
    int *st, *bkt;
    cudaGetSymbolAddress((void**)&x1,   g_x1);
    cudaGetSymbolAddress((void**)&x2,   g_x2);
    cudaGetSymbolAddress((void**)&xn,   g_xn);
    cudaGetSymbolAddress((void**)&qk,   g_qk);
    cudaGetSymbolAddress((void**)&v,    g_v);
    cudaGetSymbolAddress((void**)&ao,   g_ao);
    cudaGetSymbolAddress((void**)&ffh,  g_ffh);
    cudaGetSymbolAddress((void**)&bo,   g_bo);
    cudaGetSymbolAddress((void**)&slog, g_slog);
    cudaGetSymbolAddress((void**)&pool, g_pool);
    cudaGetSymbolAddress((void**)&st,   g_st);
    cudaGetSymbolAddress((void**)&bkt,  g_bkt);

    const int ATTN_SMEM = (64*65 + 64*65 + 64*132 + 128)*4 + 128*4;
    cudaFuncSetAttribute(attn_kernel, cudaFuncAttributeMaxDynamicSharedMemorySize, ATTN_SMEM);

    const int M = Bb*Tt;

    embed_kernel<<<(Bb*Tt*Dd + 255)/256, 256>>>(ids, tok, pos, x1, x2);

    for (int l = 0; l < DEPTHL; l++) {
        const float* Wqk_l = Wqk + (size_t)l*Dd*Dd;
        const float* Wv_l  = Wv  + (size_t)l*Dd*Dd;
        const float* Wo_l  = Wo  + (size_t)l*Dd*Dd;
        const float* W1_l  = W1  + (size_t)l*Dd*FFf;
        const float* W2_l  = W2  + (size_t)l*FFf*Dd;
        const float* b1_l  = b1  + (size_t)l*FFf;
        const float* b2_l  = b2  + (size_t)l*Dd;
        const float* rot_l = rot + (size_t)l*DHh*64;

        // attention block: x1 += attn(LN(x2)) @ Wo
        ln_kernel<<<M, 256>>>(x2, nullptr, xn, lag + l*Dd, lab + l*Dd);
        // fused QKV: logical N=1024 split into qk (Wqk) and v (Wv)
        gemm_kernel<0><<<dim3(1024/128, M/128), 256>>>(xn, Wqk_l, nullptr, qk,
                                                       M, Dd, Wv_l, v, Dd, Dd);
        hash_kernel<<<(BHn*NHh*Tt)/256, 256>>>(rot_l, qk, bkt);
        sort_kernel<<<BHn*NHh, 512>>>(bkt, st);
        attn_kernel<<<dim3(NC, BHn), 256, ATTN_SMEM>>>(st, qk, v, slog, bo);
        combine_kernel<<<(BHn*Tt*16)/256, 256>>>(slog, bo, ao);
        gemm_kernel<3><<<dim3(Dd/128, M/128), 256>>>(ao, Wo_l, nullptr, x1,
                                                     M, Dd, nullptr, nullptr, 0, Dd);

        // feed-forward block: x2 += gelu(LN(x1)@W1 + b1) @ W2 + b2
        ln_kernel<<<M, 256>>>(x1, nullptr, xn, lfg + l*Dd, lfb + l*Dd);
        gemm_kernel<1><<<dim3(FFf/128, M/128), 256>>>(xn, W1_l, b1_l, ffh,
                                                      M, Dd, nullptr, nullptr, 0, FFf);
        gemm_kernel<4><<<dim3(Dd/128, M/128), 256>>>(ffh, W2_l, b2_l, x2,
                                                     M, FFf, nullptr, nullptr, 0, Dd);
    }

    // final: 0.5*(x1+x2) -> LN -> mean over T -> @ Wfc
    ln_kernel<<<M, 256>>>(x1, x2, xn, lng, lnb);
    pool_kernel<<<Bb, Dd>>>(xn, pool);
    fc_kernel<<<Bb, Dd>>>(pool, Wfc, out);
}

// round 13
// speedup vs baseline: 1.2384x; 1.1369x over previous
#include <cuda_runtime.h>
#include <math.h>
#include <stdint.h>

#define Bb 8
#define Tt 1024
#define Dd 512
#define Hh 8
#define DHh 64
#define DEPTHL 8
#define FFf 2048
#define NHh 8
#define BSz 64
#define NBk 16
#define NC (NHh*NBk)
#define BHn (Bb*Hh)
#define SEG (NHh*Tt)

// ---------------- scratch ----------------
__device__ float g_x1[Bb*Tt*Dd];
__device__ float g_x2[Bb*Tt*Dd];
__device__ float g_xn[Bb*Tt*Dd];
__device__ float g_qk[Bb*Tt*Dd];
__device__ float g_v [Bb*Tt*Dd];
__device__ float g_ao[Bb*Tt*Dd];
__device__ float g_ffh[Bb*Tt*FFf];
__device__ float g_bo[(size_t)BHn*NHh*Tt*DHh];
__device__ float g_slog[BHn*NHh*Tt];
__device__ int   g_st [BHn*SEG];
__device__ int   g_bkt[BHn*SEG];
__device__ float g_pool[Bb*Dd];

// ---------------- helpers ----------------
__device__ __forceinline__ float gelu_fast(float x) {
    float u = 0.7978845608028654f*(x + 0.044715f*x*x*x);
    float t = 1.f - 2.f/(__expf(2.f*u) + 1.f);
    return 0.5f*x*(1.f + t);
}

__device__ __forceinline__ float blockReduceSum256(float val, float* red) {
    #pragma unroll
    for (int o = 16; o; o >>= 1) val += __shfl_xor_sync(0xffffffffu, val, o);
    int w = threadIdx.x >> 5;
    if ((threadIdx.x & 31) == 0) red[w] = val;
    __syncthreads();
    float r = (threadIdx.x < 8) ? red[threadIdx.x] : 0.f;
    if (threadIdx.x < 32) {
        #pragma unroll
        for (int o = 4; o; o >>= 1) r += __shfl_xor_sync(0xffffffffu, r, o);
        if (threadIdx.x == 0) red[0] = r;
    }
    __syncthreads();
    float out = red[0];
    __syncthreads();
    return out;
}

__device__ __forceinline__ unsigned f2tf32(float x) {
    unsigned r;
    asm("cvt.rna.tf32.f32 %0, %1;" : "=r"(r) : "f"(x));
    return r;
}

__device__ __forceinline__ void mma_tf32(float* c,
    unsigned a0, unsigned a1, unsigned a2, unsigned a3,
    unsigned b0, unsigned b1) {
    asm volatile(
        "mma.sync.aligned.m16n8k8.row.col.f32.tf32.tf32.f32 "
        "{%0,%1,%2,%3}, {%4,%5,%6,%7}, {%8,%9}, {%0,%1,%2,%3};"
        : "+f"(c[0]), "+f"(c[1]), "+f"(c[2]), "+f"(c[3])
        : "r"(a0), "r"(a1), "r"(a2), "r"(a3), "r"(b0), "r"(b1));
}

__device__ __forceinline__ void cp16(void* smem, const void* gmem) {
    unsigned s = (unsigned)__cvta_generic_to_shared(smem);
    asm volatile("cp.async.ca.shared.global [%0], [%1], 16;" :: "r"(s), "l"(gmem));
}

// ---------------- embedding ----------------
__global__ void embed_kernel(const int* __restrict__ ids,
                             const float* __restrict__ tok,
                             const float* __restrict__ pos,
                             float* __restrict__ x1, float* __restrict__ x2) {
    int i = blockIdx.x*256 + threadIdx.x;
    if (i >= Bb*Tt*Dd) return;
    int d = i & (Dd-1);
    int bt = i >> 9;
    int t = bt & (Tt-1);
    int id = ids[bt];
    if (id < 0) id = 0;
    if (id >= 6400) id = 6399;
    float v = tok[(size_t)id*Dd + d] + pos[t*Dd + d];
    x1[i] = v; x2[i] = v;
}

// ---------------- layernorm ----------------
__global__ void ln_kernel(const float* __restrict__ x, const float* __restrict__ xb,
                          float* __restrict__ y,
                          const float* __restrict__ g, const float* __restrict__ bia) {
    __shared__ float red[8];
    int row = blockIdx.x;
    int i0 = row*Dd + threadIdx.x;
    float v0, v1;
    if (xb) { v0 = 0.5f*(x[i0] + xb[i0]); v1 = 0.5f*(x[i0+256] + xb[i0+256]); }
    else    { v0 = x[i0];                 v1 = x[i0+256]; }
    float s = blockReduceSum256(v0+v1, red);
    float mean = s * (1.f/512.f);
    float d0 = v0 - mean, d1 = v1 - mean;
    float s2 = blockReduceSum256(d0*d0 + d1*d1, red);
    float inv = rsqrtf(s2*(1.f/512.f) + 1e-5f);
    y[i0]     = d0*inv*g[threadIdx.x]     + bia[threadIdx.x];
    y[i0+256] = d1*inv*g[threadIdx.x+256] + bia[threadIdx.x+256];
}

// ---------------- tensor-core GEMM (3xTF32, cp.async double-buffered) ----------------
template<int EPI>
__global__ void __launch_bounds__(256) gemm_kernel(const float* __restrict__ A,
                            const float* __restrict__ Bm,
                            const float* __restrict__ bias, float* __restrict__ C,
                            int M, int K,
                            const float* __restrict__ Bm2, float* __restrict__ C2,
                            int nHalf, int Nplain) {
    __shared__ float As[2][128][20];
    __shared__ float Bs[2][16][136];

    const int tid  = threadIdx.x;
    const int lane = tid & 31;
    const int warp = tid >> 5;
    const int wm = warp & 1;
    const int wn = warp >> 1;
    const int gid = lane >> 2;
    const int qid = lane & 3;
    const int bm = blockIdx.y*128;

    const float* Bu = Bm;
    float* Cu = C;
    int bn = blockIdx.x*128;
    int Nld = Nplain;
    if (Bm2 != nullptr) {
        Nld = nHalf;
        if (bn >= nHalf) { Bu = Bm2; Cu = C2; bn -= nHalf; }
    }

    float c[4][4][4];
    #pragma unroll
    for (int mt = 0; mt < 4; mt++)
        #pragma unroll
        for (int nt = 0; nt < 4; nt++)
            #pragma unroll
            for (int e = 0; e < 4; e++) c[mt][nt][e] = 0.f;

    const int aM  = (tid + 0)   >> 2, aO  = ((tid + 0)   & 3)*4;
    const int aM2 = (tid + 256) >> 2, aO2 = ((tid + 256) & 3)*4;
    const int bKk  = (tid + 0)   >> 5, bNo  = ((tid + 0)   & 31)*4;
    const int bKk2 = (tid + 256) >> 5, bNo2 = ((tid + 256) & 31)*4;

    const int nk = K >> 4;

    {
        cp16(&As[0][aM ][aO ], A + (size_t)(bm + aM )*K + aO );
        cp16(&As[0][aM2][aO2], A + (size_t)(bm + aM2)*K + aO2);
        cp16(&Bs[0][bKk ][bNo ], Bu + (size_t)bKk *Nld + bn + bNo );
        cp16(&Bs[0][bKk2][bNo2], Bu + (size_t)bKk2*Nld + bn + bNo2);
        asm volatile("cp.async.commit_group;");
        asm volatile("cp.async.wait_group 0;");
    }
    __syncthreads();

    for (int kt = 0; kt < nk; kt++) {
        const int cur = kt & 1;
        if (kt + 1 < nk) {
            const int nxt = cur ^ 1;
            int k0 = (kt + 1)*16;
            cp16(&As[nxt][aM ][aO ], A + (size_t)(bm + aM )*K + k0 + aO );
            cp16(&As[nxt][aM2][aO2], A + (size_t)(bm + aM2)*K + k0 + aO2);
            cp16(&Bs[nxt][bKk ][bNo ], Bu + (size_t)(k0 + bKk )*Nld + bn + bNo );
            cp16(&Bs[nxt][bKk2][bNo2], Bu + (size_t)(k0 + bKk2)*Nld + bn + bNo2);
            asm volatile("cp.async.commit_group;");
        }

        #pragma unroll
        for (int ks = 0; ks < 2; ks++) {
            const int k8 = ks*8;
            unsigned ahi[4][4], alo[4][4];
            #pragma unroll
            for (int mt = 0; mt < 4; mt++) {
                int mc = wm*64 + mt*16;
                float x0 = As[cur][mc+gid  ][k8+qid];
                float x1 = As[cur][mc+gid+8][k8+qid];
                float x2 = As[cur][mc+gid  ][k8+qid+4];
                float x3 = As[cur][mc+gid+8][k8+qid+4];
                ahi[mt][0] = f2tf32(x0); alo[mt][0] = f2tf32(x0 - __uint_as_float(ahi[mt][0]));
                ahi[mt][1] = f2tf32(x1); alo[mt][1] = f2tf32(x1 - __uint_as_float(ahi[mt][1]));
                ahi[mt][2] = f2tf32(x2); alo[mt][2] = f2tf32(x2 - __uint_as_float(ahi[mt][2]));
                ahi[mt][3] = f2tf32(x3); alo[mt][3] = f2tf32(x3 - __uint_as_float(ahi[mt][3]));
            }
            #pragma unroll
            for (int nt = 0; nt < 4; nt++) {
                int nc = wn*32 + nt*8;
                float y0 = Bs[cur][k8+qid  ][nc+gid];
                float y1 = Bs[cur][k8+qid+4][nc+gid];
                unsigned bh0 = f2tf32(y0), bl0 = f2tf32(y0 - __uint_as_float(bh0));
                unsigned bh1 = f2tf32(y1), bl1 = f2tf32(y1 - __uint_as_float(bh1));
                #pragma unroll
                for (int mt = 0; mt < 4; mt++) {
                    mma_tf32(c[mt][nt], ahi[mt][0],ahi[mt][1],ahi[mt][2],ahi[mt][3], bh0, bh1);
                    mma_tf32(c[mt][nt], ahi[mt][0],ahi[mt][1],ahi[mt][2],ahi[mt][3], bl0, bl1);
                    mma_tf32(c[mt][nt], alo[mt][0],alo[mt][1],alo[mt][2],alo[mt][3], bh0, bh1);
                }
            }
        }
        asm volatile("cp.async.wait_group 0;");
        __syncthreads();
    }

    #pragma unroll
    for (int mt = 0; mt < 4; mt++) {
        #pragma unroll
        for (int nt = 0; nt < 4; nt++) {
            int row = bm + wm*64 + mt*16 + gid;
            int col = bn + wn*32 + nt*8 + qid*2;
            float* p0 = Cu + (size_t)row*Nld + col;
            float* p1 = Cu + (size_t)(row+8)*Nld + col;
            float v00 = c[mt][nt][0], v01 = c[mt][nt][1];
            float v10 = c[mt][nt][2], v11 = c[mt][nt][3];
            if (EPI == 0) {
                p0[0] = v00; p0[1] = v01; p1[0] = v10; p1[1] = v11;
            } else if (EPI == 1) {
                float b0v = bias[col], b1v = bias[col+1];
                p0[0] = gelu_fast(v00 + b0v); p0[1] = gelu_fast(v01 + b1v);
                p1[0] = gelu_fast(v10 + b0v); p1[1] = gelu_fast(v11 + b1v);
            } else if (EPI == 3) {
                p0[0] += v00; p0[1] += v01; p1[0] += v10; p1[1] += v11;
            } else {
                float b0v = bias[col], b1v = bias[col+1];
                p0[0] += v00 + b0v; p0[1] += v01 + b1v;
                p1[0] += v10 + b0v; p1[1] += v11 + b1v;
            }
        }
    }
}

// ---------------- LSH hashing v2: one block = 64 tokens x all 8 rounds ----------------
__global__ void hash_kernel(const float* __restrict__ rot,
                            const float* __restrict__ qk, int* __restrict__ bkt) {
    __shared__ float rs[64*64];
    __shared__ float sq[64][68];
    int blk = blockIdx.x;
    int bh = blk >> 4;
    int t0 = (blk & 15)*64;
    int b = bh >> 3, h = bh & 7;
    int tid = threadIdx.x;
    for (int i = tid; i < 64*64; i += 256) rs[i] = rot[i];
    for (int i = tid; i < 64*16; i += 256) {
        int r = i >> 4, c4 = (i & 15)*4;
        float4 q4 = *(const float4*)&qk[(size_t)(b*Tt + t0 + r)*Dd + h*DHh + c4];
        sq[r][c4+0] = q4.x; sq[r][c4+1] = q4.y; sq[r][c4+2] = q4.z; sq[r][c4+3] = q4.w;
    }
    __syncthreads();
    #pragma unroll
    for (int j = 0; j < 2; j++) {
        int idx = tid + j*256;
        int tl = idx >> 3, nh = idx & 7;
        float rv[8];
        #pragma unroll
        for (int r = 0; r < 8; r++) rv[r] = 0.f;
        #pragma unroll 4
        for (int d = 0; d < 64; d++) {
            float q = sq[tl][d];
            const float* rp = &rs[d*64 + nh*8];
            #pragma unroll
            for (int r = 0; r < 8; r++) rv[r] += q*rp[r];
        }
        int best = 0; float bv = rv[0];
        #pragma unroll
        for (int r = 1; r < 8; r++) if (rv[r] > bv) { bv = rv[r]; best = r; }
        #pragma unroll
        for (int r = 0; r < 8; r++) { float nv = -rv[r]; if (nv > bv) { bv = nv; best = 8 + r; } }
        bkt[(bh*NHh + nh)*Tt + t0 + tl] = best;
    }
}

// ---------------- stable counting sort ----------------
__global__ void sort_kernel(const int* __restrict__ bkt, int* __restrict__ st) {
    __shared__ int sb[Tt];
    __shared__ int cnt[16];
    __shared__ int off[16];
    int base = blockIdx.x*Tt;
    int tid = threadIdx.x;
    for (int i = tid; i < Tt; i += 512) sb[i] = bkt[base + i];
    __syncthreads();
    int w = tid >> 5, lane = tid & 31;
    int c = 0;
    for (int it = 0; it < 32; it++) {
        unsigned m = __ballot_sync(0xffffffffu, sb[it*32 + lane] == w);
        c += __popc(m);
    }
    if (lane == 0) cnt[w] = c;
    __syncthreads();
    if (tid == 0) {
        int s = 0;
        for (int i = 0; i < 16; i++) { off[i] = s; s += cnt[i]; }
    }
    __syncthreads();
    int p = off[w];
    for (int it = 0; it < 32; it++) {
        int t = it*32 + lane;
        int bb = sb[t];
        unsigned m = __ballot_sync(0xffffffffu, bb == w);
        if (bb == w) {
            int pos = p + __popc(m & ((1u << lane) - 1u));
            st[base + pos] = t;
        }
        p += __popc(m);
    }
}

// ---------------- chunked LSH attention (tensor-core, pre-split hi/lo tiles) ----------------
__global__ void __launch_bounds__(256,2) attn_kernel(const int* __restrict__ st,
                                                   const float* __restrict__ qk,
                                                   const float* __restrict__ vg,
                                                   float* __restrict__ slog,
                                                   float* __restrict__ bo) {
    extern __shared__ float sm[];
    unsigned* qh = (unsigned*)sm;          // [64*68] hi of q tile / V half0
    unsigned* ql = qh + 64*68;             // lo
    unsigned* kh_ = ql + 64*68;            // hi of K half1 / V half1
    unsigned* kl_ = kh_ + 64*68;           // lo
    float* sd   = (float*)(kl_ + 64*68);   // [64*132] dots -> probs
    float* invs = sd + 64*132;             // [128]
    int*   posK = (int*)(invs + 128);      // [128]

    int n = blockIdx.x, bh = blockIdx.y;
    int b = bh >> 3, h = bh & 7;
    int tid = threadIdx.x;
    int nh = n >> 4;
    int segb = bh*SEG;

    const int lane = tid & 31, warp = tid >> 5;
    const int gid = lane >> 2, qid = lane & 3;

    if (tid < 128) {
        int cc = (tid < 64) ? n : ((n + NC - 1) & (NC-1));
        posK[tid] = st[segb + cc*BSz + (tid & 63)];
    }
    __syncthreads();

    // load q tile (keys half0) and K half1, split into hi/lo tf32
    for (int i = tid; i < 64*16; i += 256) {
        int r = i >> 4, c4 = (i & 15)*4;
        float4 a = *(const float4*)&qk[(size_t)(b*Tt + posK[r])*Dd + h*DHh + c4];
        float av[4] = {a.x, a.y, a.z, a.w};
        float4 k2 = *(const float4*)&qk[(size_t)(b*Tt + posK[64+r])*Dd + h*DHh + c4];
        float kv[4] = {k2.x, k2.y, k2.z, k2.w};
        #pragma unroll
        for (int e = 0; e < 4; e++) {
            unsigned hA = f2tf32(av[e]);
            qh[r*68 + c4 + e] = hA;
            ql[r*68 + c4 + e] = f2tf32(av[e] - __uint_as_float(hA));
            unsigned hK = f2tf32(kv[e]);
            kh_[r*68 + c4 + e] = hK;
            kl_[r*68 + c4 + e] = f2tf32(kv[e] - __uint_as_float(hK));
        }
    }
    __syncthreads();

    // key inverse norms (reconstruct hi+lo ~= fp32 value)
    if (tid < 128) {
        const unsigned* ph = (tid < 64) ? qh : kh_;
        const unsigned* pl = (tid < 64) ? ql : kl_;
        int r = tid & 63;
        float s = 0.f;
        #pragma unroll 8
        for (int d = 0; d < 64; d++) {
            float x = __uint_as_float(ph[r*68 + d]) + __uint_as_float(pl[r*68 + d]);
            s += x*x;
        }
        invs[tid] = 1.f/(sqrtf(s) + 1e-8f);
    }
    __syncthreads();

    // ---- QK^T: warp = (mpair, key-half, n-group) ----
    {
        const int mb  = (warp & 1)*32;
        const int khh = (warp >> 1) & 1;
        const int nb  = (warp >> 2)*32;
        const unsigned* bhp = khh ? kh_ : qh;
        const unsigned* blp = khh ? kl_ : ql;
        float c[2][4][4];
        #pragma unroll
        for (int mt = 0; mt < 2; mt++)
            #pragma unroll
            for (int nt = 0; nt < 4; nt++)
                #pragma unroll
                for (int e = 0; e < 4; e++) c[mt][nt][e] = 0.f;

        #pragma unroll
        for (int kt = 0; kt < 8; kt++) {
            int k0 = kt*8;
            unsigned ah[2][4], al[2][4];
            #pragma unroll
            for (int mt = 0; mt < 2; mt++) {
                int r0 = (mb + mt*16 + gid)*68;
                int r1 = r0 + 8*68;
                ah[mt][0] = qh[r0 + k0+qid];   al[mt][0] = ql[r0 + k0+qid];
                ah[mt][1] = qh[r1 + k0+qid];   al[mt][1] = ql[r1 + k0+qid];
                ah[mt][2] = qh[r0 + k0+qid+4]; al[mt][2] = ql[r0 + k0+qid+4];
                ah[mt][3] = qh[r1 + k0+qid+4]; al[mt][3] = ql[r1 + k0+qid+4];
            }
            #pragma unroll
            for (int nt = 0; nt < 4; nt++) {
                int kr = (nb + nt*8 + gid)*68;
                unsigned b0h = bhp[kr + k0+qid],   b0l = blp[kr + k0+qid];
                unsigned b1h = bhp[kr + k0+qid+4], b1l = blp[kr + k0+qid+4];
                #pragma unroll
                for (int mt = 0; mt < 2; mt++) {
                    mma_tf32(c[mt][nt], ah[mt][0],ah[mt][1],ah[mt][2],ah[mt][3], b0h, b1h);
                    mma_tf32(c[mt][nt], ah[mt][0],ah[mt][1],ah[mt][2],ah[mt][3], b0l, b1l);
                    mma_tf32(c[mt][nt], al[mt][0],al[mt][1],al[mt][2],al[mt][3], b0h, b1h);
                }
            }
        }
        #pragma unroll
        for (int mt = 0; mt < 2; mt++) {
            int r0 = mb + mt*16 + gid;
            int pq0 = posK[r0], pq1 = posK[r0+8];
            #pragma unroll
            for (int nt = 0; nt < 4; nt++) {
                int col = khh*64 + nb + nt*8 + qid*2;
                float is0 = invs[col]*0.125f, is1 = invs[col+1]*0.125f;
                int pk0 = posK[col], pk1 = posK[col+1];
                float s00 = c[mt][nt][0]*is0; if (pq0 == pk0) s00 = -5e4f;
                float s01 = c[mt][nt][1]*is1; if (pq0 == pk1) s01 = -5e4f;
                float s10 = c[mt][nt][2]*is0; if (pq1 == pk0) s10 = -5e4f;
                float s11 = c[mt][nt][3]*is1; if (pq1 == pk1) s11 = -5e4f;
                sd[r0*132 + col] = s00;     sd[r0*132 + col+1] = s01;
                sd[(r0+8)*132 + col] = s10; sd[(r0+8)*132 + col+1] = s11;
            }
        }
    }
    __syncthreads();

    // ---- softmax per row ----
    {
        int r = tid >> 2, c4 = tid & 3;
        float vals[32];
        float mx = -1e30f;
        #pragma unroll
        for (int i = 0; i < 32; i++) { vals[i] = sd[r*132 + i*4 + c4]; mx = fmaxf(mx, vals[i]); }
        mx = fmaxf(mx, __shfl_xor_sync(0xffffffffu, mx, 1));
        mx = fmaxf(mx, __shfl_xor_sync(0xffffffffu, mx, 2));
        float se = 0.f;
        #pragma unroll
        for (int i = 0; i < 32; i++) { vals[i] = __expf(vals[i] - mx); se += vals[i]; }
        se += __shfl_xor_sync(0xffffffffu, se, 1);
        se += __shfl_xor_sync(0xffffffffu, se, 2);
        if (c4 == 0) slog[((size_t)bh*NHh + nh)*Tt + posK[r]] = mx + __logf(se);
        float inv_se = 1.f/se;
        #pragma unroll
        for (int i = 0; i < 32; i++) sd[r*132 + i*4 + c4] = vals[i]*inv_se;
    }
    __syncthreads();

    // ---- load V halves, split hi/lo into the same arrays ----
    for (int i = tid; i < 64*16; i += 256) {
        int r = i >> 4, c4 = (i & 15)*4;
        float4 a = *(const float4*)&vg[(size_t)(b*Tt + posK[r])*Dd + h*DHh + c4];
        float av[4] = {a.x, a.y, a.z, a.w};
        float4 k2 = *(const float4*)&vg[(size_t)(b*Tt + posK[64+r])*Dd + h*DHh + c4];
        float kv[4] = {k2.x, k2.y, k2.z, k2.w};
        #pragma unroll
        for (int e = 0; e < 4; e++) {
            unsigned hA = f2tf32(av[e]);
            qh[r*68 + c4 + e] = hA;
            ql[r*68 + c4 + e] = f2tf32(av[e] - __uint_as_float(hA));
            unsigned hK = f2tf32(kv[e]);
            kh_[r*68 + c4 + e] = hK;
            kl_[r*68 + c4 + e] = f2tf32(kv[e] - __uint_as_float(hK));
        }
    }
    __syncthreads();

    // ---- PV: warp = (mpair, d-group) ----
    {
        const int mb = (warp & 1)*32;
        const int db = ((warp >> 1) & 3)*16;
        float c[2][2][4];
        #pragma unroll
        for (int mt = 0; mt < 2; mt++)
            #pragma unroll
            for (int nt = 0; nt < 2; nt++)
                #pragma unroll
                for (int e = 0; e < 4; e++) c[mt][nt][e] = 0.f;

        #pragma unroll
        for (int kt = 0; kt < 16; kt++) {
            int k0 = kt*8;
            const unsigned* vh = (k0 < 64) ? qh : kh_;
            const unsigned* vl = (k0 < 64) ? ql : kl_;
            int kk = k0 & 63;
            unsigned ah[2][4], al[2][4];
            #pragma unroll
            for (int mt = 0; mt < 2; mt++) {
                int r0 = (mb + mt*16 + gid)*132;
                int r1 = r0 + 8*132;
                float x0 = sd[r0 + k0+qid];
                float x1 = sd[r1 + k0+qid];
                float x2 = sd[r0 + k0+qid+4];
                float x3 = sd[r1 + k0+qid+4];
                ah[mt][0] = f2tf32(x0); al[mt][0] = f2tf32(x0 - __uint_as_float(ah[mt][0]));
                ah[mt][1] = f2tf32(x1); al[mt][1] = f2tf32(x1 - __uint_as_float(ah[mt][1]));
                ah[mt][2] = f2tf32(x2); al[mt][2] = f2tf32(x2 - __uint_as_float(ah[mt][2]));
                ah[mt][3] = f2tf32(x3); al[mt][3] = f2tf32(x3 - __uint_as_float(ah[mt][3]));
            }
            #pragma unroll
            for (int nt = 0; nt < 2; nt++) {
                int d = db + nt*8 + gid;
                unsigned b0h = vh[(kk+qid)*68 + d],   b0l = vl[(kk+qid)*68 + d];
                unsigned b1h = vh[(kk+qid+4)*68 + d], b1l = vl[(kk+qid+4)*68 + d];
                #pragma unroll
                for (int mt = 0; mt < 2; mt++) {
                    mma_tf32(c[mt][nt], ah[mt][0],ah[mt][1],ah[mt][2],ah[mt][3], b0h, b1h);
                    mma_tf32(c[mt][nt], ah[mt][0],ah[mt][1],ah[mt][2],ah[mt][3], b0l, b1l);
                    mma_tf32(c[mt][nt], al[mt][0],al[mt][1],al[mt][2],al[mt][3], b0h, b1h);
                }
            }
        }
        size_t base0 = ((size_t)bh*NHh + nh)*Tt;
        #pragma unroll
        for (int mt = 0; mt < 2; mt++) {
            int r0 = mb + mt*16 + gid;
            float* bo0 = &bo[(base0 + posK[r0])*DHh];
            float* bo1 = &bo[(base0 + posK[r0+8])*DHh];
            #pragma unroll
            for (int nt = 0; nt < 2; nt++) {
                int col = db + nt*8 + qid*2;
                bo0[col] = c[mt][nt][0]; bo0[col+1] = c[mt][nt][1];
                bo1[col] = c[mt][nt][2]; bo1[col+1] = c[mt][nt][3];
            }
        }
    }
}

// ---------------- combine ----------------
__global__ void combine_kernel(const float* __restrict__ slog,
                               const float* __restrict__ bo,
                               float* __restrict__ ao) {
    int idx = blockIdx.x*256 + threadIdx.x;
    if (idx >= BHn*Tt*16) return;
    int d4 = (idx & 15)*4;
    int t  = (idx >> 4) & (Tt-1);
    int bh = idx >> 14;
    float lg[NHh];
    float mx = -1e30f;
    #pragma unroll
    for (int i = 0; i < NHh; i++) {
        lg[i] = slog[((size_t)bh*NHh + i)*Tt + t];
        mx = fmaxf(mx, lg[i]);
    }
    float se = 0.f;
    #pragma unroll
    for (int i = 0; i < NHh; i++) { lg[i] = __expf(lg[i] - mx); se += lg[i]; }
    float inv = 1.f/se;
    float4 out = make_float4(0.f, 0.f, 0.f, 0.f);
    #pragma unroll
    for (int i = 0; i < NHh; i++) {
        float w = lg[i]*inv;
        float4 bv = *(const float4*)&bo[(((size_t)bh*NHh + i)*Tt + t)*DHh + d4];
        out.x += w*bv.x; out.y += w*bv.y; out.z += w*bv.z; out.w += w*bv.w;
    }
    int b = bh >> 3, h = bh & 7;
    *(float4*)&ao[(size_t)(b*Tt + t)*Dd + h*DHh + d4] = out;
}

// ---------------- pooling + fc ----------------
__global__ void pool_kernel(const float* __restrict__ xn, float* __restrict__ pool) {
    int b = blockIdx.x, d = threadIdx.x;
    float s = 0.f;
    for (int t = 0; t < Tt; t++) s += xn[(size_t)(b*Tt + t)*Dd + d];
    pool[b*Dd + d] = s * (1.f/(float)Tt);
}

__global__ void fc_kernel(const float* __restrict__ pool,
                          const float* __restrict__ Wfc, float* __restrict__ out) {
    int b = blockIdx.x, n = threadIdx.x;
    float s = 0.f;
    for (int kk = 0; kk < Dd; kk++) s += pool[b*Dd + kk]*Wfc[kk*Dd + n];
    out[b*Dd + n] = s;
}

// ---------------- orchestration ----------------
extern "C" void kernel_launch(void* const* d_in, const int* in_sizes, int n_in,
                              void* d_out, int out_size) {
    const int*   ids = (const int*)  d_in[0];
    const float* tok = (const float*)d_in[1];
    const float* pos = (const float*)d_in[2];
    const float* lag = (const float*)d_in[3];
    const float* lab = (const float*)d_in[4];
    const float* Wqk = (const float*)d_in[5];
    const float* Wv  = (const float*)d_in[6];
    const float* Wo  = (const float*)d_in[7];
    const float* lfg = (const float*)d_in[8];
    const float* lfb = (const float*)d_in[9];
    const float* W1  = (const float*)d_in[10];
    const float* b1  = (const float*)d_in[11];
    const float* W2  = (const float*)d_in[12];
    const float* b2  = (const float*)d_in[13];
    const float* lng = (const float*)d_in[14];
    const float* lnb = (const float*)d_in[15];
    const float* Wfc = (const float*)d_in[16];
    const float* rot = (const float*)d_in[17];
    float* out = (float*)d_out;

    float *x1, *x2, *xn, *qk, *v, *ao, *ffh, *bo, *slog, *pool;
    int *st, *bkt;
    cudaGetSymbolAddress((void**)&x1,   g_x1);
    cudaGetSymbolAddress((void**)&x2,   g_x2);
    cudaGetSymbolAddress((void**)&xn,   g_xn);
    cudaGetSymbolAddress((void**)&qk,   g_qk);
    cudaGetSymbolAddress((void**)&v,    g_v);
    cudaGetSymbolAddress((void**)&ao,   g_ao);
    cudaGetSymbolAddress((void**)&ffh,  g_ffh);
    cudaGetSymbolAddress((void**)&bo,   g_bo);
    cudaGetSymbolAddress((void**)&slog, g_slog);
    cudaGetSymbolAddress((void**)&pool, g_pool);
    cudaGetSymbolAddress((void**)&st,   g_st);
    cudaGetSymbolAddress((void**)&bkt,  g_bkt);

    const int ATTN_SMEM = 4*64*68*4 + 64*132*4 + 128*4 + 128*4;   // 104448
    cudaFuncSetAttribute(attn_kernel, cudaFuncAttributeMaxDynamicSharedMemorySize, ATTN_SMEM);

    const int M = Bb*Tt;

    embed_kernel<<<(Bb*Tt*Dd + 255)/256, 256>>>(ids, tok, pos, x1, x2);

    for (int l = 0; l < DEPTHL; l++) {
        const float* Wqk_l = Wqk + (size_t)l*Dd*Dd;
        const float* Wv_l  = Wv  + (size_t)l*Dd*Dd;
        const float* Wo_l  = Wo  + (size_t)l*Dd*Dd;
        const float* W1_l  = W1  + (size_t)l*Dd*FFf;
        const float* W2_l  = W2  + (size_t)l*FFf*Dd;
        const float* b1_l  = b1  + (size_t)l*FFf;
        const float* b2_l  = b2  + (size_t)l*Dd;
        const float* rot_l = rot + (size_t)l*DHh*64;

        // attention block: x1 += attn(LN(x2)) @ Wo
        ln_kernel<<<M, 256>>>(x2, nullptr, xn, lag + l*Dd, lab + l*Dd);
        gemm_kernel<0><<<dim3(1024/128, M/128), 256>>>(xn, Wqk_l, nullptr, qk,
                                                       M, Dd, Wv_l, v, Dd, Dd);
        hash_kernel<<<BHn*16, 256>>>(rot_l, qk, bkt);
        sort_kernel<<<BHn*NHh, 512>>>(bkt, st);
        attn_kernel<<<dim3(NC, BHn), 256, ATTN_SMEM>>>(st, qk, v, slog, bo);
        combine_kernel<<<(BHn*Tt*16)/256, 256>>>(slog, bo, ao);
        gemm_kernel<3><<<dim3(Dd/128, M/128), 256>>>(ao, Wo_l, nullptr, x1,
                                                     M, Dd, nullptr, nullptr, 0, Dd);

        // feed-forward block: x2 += gelu(LN(x1)@W1 + b1) @ W2 + b2
        ln_kernel<<<M, 256>>>(x1, nullptr, xn, lfg + l*Dd, lfb + l*Dd);
        gemm_kernel<1><<<dim3(FFf/128, M/128), 256>>>(xn, W1_l, b1_l, ffh,
                                                      M, Dd, nullptr, nullptr, 0, FFf);
        gemm_kernel<4><<<dim3(Dd/128, M/128), 256>>>(ffh, W2_l, b2_l, x2,
                                                     M, FFf, nullptr, nullptr, 0, Dd);
    }

    // final: 0.5*(x1+x2) -> LN -> mean over T -> @ Wfc
    ln_kernel<<<M, 256>>>(x1, x2, xn, lng, lnb);
    pool_kernel<<<Bb, Dd>>>(xn, pool);
    fc_kernel<<<Bb, Dd>>>(pool, Wfc, out);
}

// round 14
// speedup vs baseline: 1.6153x; 1.3043x over previous
#include <cuda_runtime.h>
#include <math.h>
#include <stdint.h>

#define Bb 8
#define Tt 1024
#define Dd 512
#define Hh 8
#define DHh 64
#define DEPTHL 8
#define FFf 2048
#define NHh 8
#define BSz 64
#define NBk 16
#define NC (NHh*NBk)
#define BHn (Bb*Hh)
#define SEG (NHh*Tt)

// ---------------- scratch ----------------
__device__ float g_x1[Bb*Tt*Dd];
__device__ float g_x2[Bb*Tt*Dd];
__device__ float g_xn[Bb*Tt*Dd];
__device__ float g_qk[Bb*Tt*Dd];
__device__ float g_v [Bb*Tt*Dd];
__device__ float g_ao[Bb*Tt*Dd];
__device__ float g_ffh[Bb*Tt*FFf];
__device__ float g_bo[(size_t)BHn*NHh*Tt*DHh];
__device__ float g_slog[BHn*NHh*Tt];
__device__ int   g_st [BHn*SEG];
__device__ int   g_bkt[BHn*SEG];
__device__ float g_pool[Bb*Dd];

// ---------------- helpers ----------------
__device__ __forceinline__ float gelu_fast(float x) {
    float u = 0.7978845608028654f*(x + 0.044715f*x*x*x);
    float t = 1.f - 2.f/(__expf(2.f*u) + 1.f);
    return 0.5f*x*(1.f + t);
}

__device__ __forceinline__ float blockReduceSum256(float val, float* red) {
    #pragma unroll
    for (int o = 16; o; o >>= 1) val += __shfl_xor_sync(0xffffffffu, val, o);
    int w = threadIdx.x >> 5;
    if ((threadIdx.x & 31) == 0) red[w] = val;
    __syncthreads();
    float r = (threadIdx.x < 8) ? red[threadIdx.x] : 0.f;
    if (threadIdx.x < 32) {
        #pragma unroll
        for (int o = 4; o; o >>= 1) r += __shfl_xor_sync(0xffffffffu, r, o);
        if (threadIdx.x == 0) red[0] = r;
    }
    __syncthreads();
    float out = red[0];
    __syncthreads();
    return out;
}

__device__ __forceinline__ unsigned f2tf32(float x) {
    unsigned r;
    asm("cvt.rna.tf32.f32 %0, %1;" : "=r"(r) : "f"(x));
    return r;
}

__device__ __forceinline__ void mma_tf32(float* c,
    unsigned a0, unsigned a1, unsigned a2, unsigned a3,
    unsigned b0, unsigned b1) {
    asm volatile(
        "mma.sync.aligned.m16n8k8.row.col.f32.tf32.tf32.f32 "
        "{%0,%1,%2,%3}, {%4,%5,%6,%7}, {%8,%9}, {%0,%1,%2,%3};"
        : "+f"(c[0]), "+f"(c[1]), "+f"(c[2]), "+f"(c[3])
        : "r"(a0), "r"(a1), "r"(a2), "r"(a3), "r"(b0), "r"(b1));
}

__device__ __forceinline__ void mma_bf16(float* c,
    unsigned a0, unsigned a1, unsigned a2, unsigned a3,
    unsigned b0, unsigned b1) {
    asm volatile(
        "mma.sync.aligned.m16n8k16.row.col.f32.bf16.bf16.f32 "
        "{%0,%1,%2,%3}, {%4,%5,%6,%7}, {%8,%9}, {%0,%1,%2,%3};"
        : "+f"(c[0]), "+f"(c[1]), "+f"(c[2]), "+f"(c[3])
        : "r"(a0), "r"(a1), "r"(a2), "r"(a3), "r"(b0), "r"(b1));
}

// split (x0,x1) pair into packed bf16x2 hi and lo (residual) words.
__device__ __forceinline__ void split_pair(float x0, float x1,
                                           unsigned &hi, unsigned &lo) {
    unsigned h;
    asm("cvt.rn.bf16x2.f32 %0, %1, %2;" : "=r"(h) : "f"(x1), "f"(x0));
    float h0 = __uint_as_float(h << 16);
    float h1 = __uint_as_float(h & 0xffff0000u);
    float l0 = x0 - h0, l1 = x1 - h1;
    asm("cvt.rn.bf16x2.f32 %0, %1, %2;" : "=r"(lo) : "f"(l1), "f"(l0));
    hi = h;
}

__device__ __forceinline__ void cp16(void* smem, const void* gmem) {
    unsigned s = (unsigned)__cvta_generic_to_shared(smem);
    asm volatile("cp.async.ca.shared.global [%0], [%1], 16;" :: "r"(s), "l"(gmem));
}

// ---------------- embedding ----------------
__global__ void embed_kernel(const int* __restrict__ ids,
                             const float* __restrict__ tok,
                             const float* __restrict__ pos,
                             float* __restrict__ x1, float* __restrict__ x2) {
    int i = blockIdx.x*256 + threadIdx.x;
    if (i >= Bb*Tt*Dd) return;
    int d = i & (Dd-1);
    int bt = i >> 9;
    int t = bt & (Tt-1);
    int id = ids[bt];
    if (id < 0) id = 0;
    if (id >= 6400) id = 6399;
    float v = tok[(size_t)id*Dd + d] + pos[t*Dd + d];
    x1[i] = v; x2[i] = v;
}

// ---------------- layernorm ----------------
__global__ void ln_kernel(const float* __restrict__ x, const float* __restrict__ xb,
                          float* __restrict__ y,
                          const float* __restrict__ g, const float* __restrict__ bia) {
    __shared__ float red[8];
    int row = blockIdx.x;
    int i0 = row*Dd + threadIdx.x;
    float v0, v1;
    if (xb) { v0 = 0.5f*(x[i0] + xb[i0]); v1 = 0.5f*(x[i0+256] + xb[i0+256]); }
    else    { v0 = x[i0];                 v1 = x[i0+256]; }
    float s = blockReduceSum256(v0+v1, red);
    float mean = s * (1.f/512.f);
    float d0 = v0 - mean, d1 = v1 - mean;
    float s2 = blockReduceSum256(d0*d0 + d1*d1, red);
    float inv = rsqrtf(s2*(1.f/512.f) + 1e-5f);
    y[i0]     = d0*inv*g[threadIdx.x]     + bia[threadIdx.x];
    y[i0+256] = d1*inv*g[threadIdx.x+256] + bia[threadIdx.x+256];
}

// ---------------- tensor-core GEMM (3-term bf16 k16, cp.async double-buffered) ----------------
template<int EPI>
__global__ void __launch_bounds__(256) gemm_kernel(const float* __restrict__ A,
                            const float* __restrict__ Bm,
                            const float* __restrict__ bias, float* __restrict__ C,
                            int M, int K,
                            const float* __restrict__ Bm2, float* __restrict__ C2,
                            int nHalf, int Nplain) {
    __shared__ float As[2][128][20];
    __shared__ float Bs[2][16][132];

    const int tid  = threadIdx.x;
    const int lane = tid & 31;
    const int warp = tid >> 5;
    const int wm = warp & 1;
    const int wn = warp >> 1;
    const int gid = lane >> 2;
    const int qid = lane & 3;
    const int bm = blockIdx.y*128;

    const float* Bu = Bm;
    float* Cu = C;
    int bn = blockIdx.x*128;
    int Nld = Nplain;
    if (Bm2 != nullptr) {
        Nld = nHalf;
        if (bn >= nHalf) { Bu = Bm2; Cu = C2; bn -= nHalf; }
    }

    float c[4][4][4];
    #pragma unroll
    for (int mt = 0; mt < 4; mt++)
        #pragma unroll
        for (int nt = 0; nt < 4; nt++)
            #pragma unroll
            for (int e = 0; e < 4; e++) c[mt][nt][e] = 0.f;

    const int aM  = (tid + 0)   >> 2, aO  = ((tid + 0)   & 3)*4;
    const int aM2 = (tid + 256) >> 2, aO2 = ((tid + 256) & 3)*4;
    const int bKk  = (tid + 0)   >> 5, bNo  = ((tid + 0)   & 31)*4;
    const int bKk2 = (tid + 256) >> 5, bNo2 = ((tid + 256) & 31)*4;

    const int nk = K >> 4;

    {
        cp16(&As[0][aM ][aO ], A + (size_t)(bm + aM )*K + aO );
        cp16(&As[0][aM2][aO2], A + (size_t)(bm + aM2)*K + aO2);
        cp16(&Bs[0][bKk ][bNo ], Bu + (size_t)bKk *Nld + bn + bNo );
        cp16(&Bs[0][bKk2][bNo2], Bu + (size_t)bKk2*Nld + bn + bNo2);
        asm volatile("cp.async.commit_group;");
        asm volatile("cp.async.wait_group 0;");
    }
    __syncthreads();

    for (int kt = 0; kt < nk; kt++) {
        const int cur = kt & 1;
        if (kt + 1 < nk) {
            const int nxt = cur ^ 1;
            int k0 = (kt + 1)*16;
            cp16(&As[nxt][aM ][aO ], A + (size_t)(bm + aM )*K + k0 + aO );
            cp16(&As[nxt][aM2][aO2], A + (size_t)(bm + aM2)*K + k0 + aO2);
            cp16(&Bs[nxt][bKk ][bNo ], Bu + (size_t)(k0 + bKk )*Nld + bn + bNo );
            cp16(&Bs[nxt][bKk2][bNo2], Bu + (size_t)(k0 + bKk2)*Nld + bn + bNo2);
            asm volatile("cp.async.commit_group;");
        }

        // one full k16 mma step per K-tile
        unsigned ah[4][4], al[4][4];
        #pragma unroll
        for (int mt = 0; mt < 4; mt++) {
            int r0 = wm*64 + mt*16 + gid;
            float2 p0 = *(const float2*)&As[cur][r0  ][2*qid];
            float2 p1 = *(const float2*)&As[cur][r0+8][2*qid];
            float2 p2 = *(const float2*)&As[cur][r0  ][2*qid+8];
            float2 p3 = *(const float2*)&As[cur][r0+8][2*qid+8];
            split_pair(p0.x, p0.y, ah[mt][0], al[mt][0]);
            split_pair(p1.x, p1.y, ah[mt][1], al[mt][1]);
            split_pair(p2.x, p2.y, ah[mt][2], al[mt][2]);
            split_pair(p3.x, p3.y, ah[mt][3], al[mt][3]);
        }
        #pragma unroll
        for (int nt = 0; nt < 4; nt++) {
            int nc = wn*32 + nt*8 + gid;
            unsigned b0h, b0l, b1h, b1l;
            split_pair(Bs[cur][2*qid  ][nc], Bs[cur][2*qid+1][nc], b0h, b0l);
            split_pair(Bs[cur][2*qid+8][nc], Bs[cur][2*qid+9][nc], b1h, b1l);
            #pragma unroll
            for (int mt = 0; mt < 4; mt++) {
                mma_bf16(c[mt][nt], ah[mt][0],ah[mt][1],ah[mt][2],ah[mt][3], b0h, b1h);
                mma_bf16(c[mt][nt], ah[mt][0],ah[mt][1],ah[mt][2],ah[mt][3], b0l, b1l);
                mma_bf16(c[mt][nt], al[mt][0],al[mt][1],al[mt][2],al[mt][3], b0h, b1h);
            }
        }
        asm volatile("cp.async.wait_group 0;");
        __syncthreads();
    }

    #pragma unroll
    for (int mt = 0; mt < 4; mt++) {
        #pragma unroll
        for (int nt = 0; nt < 4; nt++) {
            int row = bm + wm*64 + mt*16 + gid;
            int col = bn + wn*32 + nt*8 + qid*2;
            float* p0 = Cu + (size_t)row*Nld + col;
            float* p1 = Cu + (size_t)(row+8)*Nld + col;
            float v00 = c[mt][nt][0], v01 = c[mt][nt][1];
            float v10 = c[mt][nt][2], v11 = c[mt][nt][3];
            if (EPI == 0) {
                p0[0] = v00; p0[1] = v01; p1[0] = v10; p1[1] = v11;
            } else if (EPI == 1) {
                float b0v = bias[col], b1v = bias[col+1];
                p0[0] = gelu_fast(v00 + b0v); p0[1] = gelu_fast(v01 + b1v);
                p1[0] = gelu_fast(v10 + b0v); p1[1] = gelu_fast(v11 + b1v);
            } else if (EPI == 3) {
                p0[0] += v00; p0[1] += v01; p1[0] += v10; p1[1] += v11;
            } else {
                float b0v = bias[col], b1v = bias[col+1];
                p0[0] += v00 + b0v; p0[1] += v01 + b1v;
                p1[0] += v10 + b0v; p1[1] += v11 + b1v;
            }
        }
    }
}

// ---------------- LSH hashing: block = 64 tokens x 8 rounds, float4 rs reads ----------------
__global__ void hash_kernel(const float* __restrict__ rot,
                            const float* __restrict__ qk, int* __restrict__ bkt) {
    __shared__ float rs[64*64];
    __shared__ float sq[64][68];
    int blk = blockIdx.x;
    int bh = blk >> 4;
    int t0 = (blk & 15)*64;
    int b = bh >> 3, h = bh & 7;
    int tid = threadIdx.x;
    for (int i = tid; i < 64*64; i += 256) rs[i] = rot[i];
    for (int i = tid; i < 64*16; i += 256) {
        int r = i >> 4, c4 = (i & 15)*4;
        float4 q4 = *(const float4*)&qk[(size_t)(b*Tt + t0 + r)*Dd + h*DHh + c4];
        sq[r][c4+0] = q4.x; sq[r][c4+1] = q4.y; sq[r][c4+2] = q4.z; sq[r][c4+3] = q4.w;
    }
    __syncthreads();
    #pragma unroll
    for (int j = 0; j < 2; j++) {
        int idx = tid + j*256;
        int tl = idx >> 3, nh = idx & 7;
        float rv[8];
        #pragma unroll
        for (int r = 0; r < 8; r++) rv[r] = 0.f;
        #pragma unroll 4
        for (int d = 0; d < 64; d++) {
            float q = sq[tl][d];
            float4 r0 = *(const float4*)&rs[d*64 + nh*8];
            float4 r1 = *(const float4*)&rs[d*64 + nh*8 + 4];
            rv[0] += q*r0.x; rv[1] += q*r0.y; rv[2] += q*r0.z; rv[3] += q*r0.w;
            rv[4] += q*r1.x; rv[5] += q*r1.y; rv[6] += q*r1.z; rv[7] += q*r1.w;
        }
        int best = 0; float bv = rv[0];
        #pragma unroll
        for (int r = 1; r < 8; r++) if (rv[r] > bv) { bv = rv[r]; best = r; }
        #pragma unroll
        for (int r = 0; r < 8; r++) { float nv = -rv[r]; if (nv > bv) { bv = nv; best = 8 + r; } }
        bkt[(bh*NHh + nh)*Tt + t0 + tl] = best;
    }
}

// ---------------- stable counting sort ----------------
__global__ void sort_kernel(const int* __restrict__ bkt, int* __restrict__ st) {
    __shared__ int sb[Tt];
    __shared__ int cnt[16];
    __shared__ int off[16];
    int base = blockIdx.x*Tt;
    int tid = threadIdx.x;
    for (int i = tid; i < Tt; i += 512) sb[i] = bkt[base + i];
    __syncthreads();
    int w = tid >> 5, lane = tid & 31;
    int c = 0;
    for (int it = 0; it < 32; it++) {
        unsigned m = __ballot_sync(0xffffffffu, sb[it*32 + lane] == w);
        c += __popc(m);
    }
    if (lane == 0) cnt[w] = c;
    __syncthreads();
    if (tid == 0) {
        int s = 0;
        for (int i = 0; i < 16; i++) { off[i] = s; s += cnt[i]; }
    }
    __syncthreads();
    int p = off[w];
    for (int it = 0; it < 32; it++) {
        int t = it*32 + lane;
        int bb = sb[t];
        unsigned m = __ballot_sync(0xffffffffu, bb == w);
        if (bb == w) {
            int pos = p + __popc(m & ((1u << lane) - 1u));
            st[base + pos] = t;
        }
        p += __popc(m);
    }
}

// ---------------- chunked LSH attention (tensor-core, pre-split hi/lo tiles) ----------------
__global__ void __launch_bounds__(256,2) attn_kernel(const int* __restrict__ st,
                                                   const float* __restrict__ qk,
                                                   const float* __restrict__ vg,
                                                   float* __restrict__ slog,
                                                   float* __restrict__ bo) {
    extern __shared__ float sm[];
    unsigned* qh = (unsigned*)sm;
    unsigned* ql = qh + 64*68;
    unsigned* kh_ = ql + 64*68;
    unsigned* kl_ = kh_ + 64*68;
    float* sd   = (float*)(kl_ + 64*68);
    float* invs = sd + 64*132;
    int*   posK = (int*)(invs + 128);

    int n = blockIdx.x, bh = blockIdx.y;
    int b = bh >> 3, h = bh & 7;
    int tid = threadIdx.x;
    int nh = n >> 4;
    int segb = bh*SEG;

    const int lane = tid & 31, warp = tid >> 5;
    const int gid = lane >> 2, qid = lane & 3;

    if (tid < 128) {
        int cc = (tid < 64) ? n : ((n + NC - 1) & (NC-1));
        posK[tid] = st[segb + cc*BSz + (tid & 63)];
    }
    __syncthreads();

    for (int i = tid; i < 64*16; i += 256) {
        int r = i >> 4, c4 = (i & 15)*4;
        float4 a = *(const float4*)&qk[(size_t)(b*Tt + posK[r])*Dd + h*DHh + c4];
        float av[4] = {a.x, a.y, a.z, a.w};
        float4 k2 = *(const float4*)&qk[(size_t)(b*Tt + posK[64+r])*Dd + h*DHh + c4];
        float kv[4] = {k2.x, k2.y, k2.z, k2.w};
        #pragma unroll
        for (int e = 0; e < 4; e++) {
            unsigned hA = f2tf32(av[e]);
            qh[r*68 + c4 + e] = hA;
            ql[r*68 + c4 + e] = f2tf32(av[e] - __uint_as_float(hA));
            unsigned hK = f2tf32(kv[e]);
            kh_[r*68 + c4 + e] = hK;
            kl_[r*68 + c4 + e] = f2tf32(kv[e] - __uint_as_float(hK));
        }
    }
    __syncthreads();

    if (tid < 128) {
        const unsigned* ph = (tid < 64) ? qh : kh_;
        const unsigned* pl = (tid < 64) ? ql : kl_;
        int r = tid & 63;
        float s = 0.f;
        #pragma unroll 8
        for (int d = 0; d < 64; d++) {
            float x = __uint_as_float(ph[r*68 + d]) + __uint_as_float(pl[r*68 + d]);
            s += x*x;
        }
        invs[tid] = 1.f/(sqrtf(s) + 1e-8f);
    }
    __syncthreads();

    {
        const int mb  = (warp & 1)*32;
        const int khh = (warp >> 1) & 1;
        const int nb  = (warp >> 2)*32;
        const unsigned* bhp = khh ? kh_ : qh;
        const unsigned* blp = khh ? kl_ : ql;
        float c[2][4][4];
        #pragma unroll
        for (int mt = 0; mt < 2; mt++)
            #pragma unroll
            for (int nt = 0; nt < 4; nt++)
                #pragma unroll
                for (int e = 0; e < 4; e++) c[mt][nt][e] = 0.f;

        #pragma unroll
        for (int kt = 0; kt < 8; kt++) {
            int k0 = kt*8;
            unsigned ah[2][4], al[2][4];
            #pragma unroll
            for (int mt = 0; mt < 2; mt++) {
                int r0 = (mb + mt*16 + gid)*68;
                int r1 = r0 + 8*68;
                ah[mt][0] = qh[r0 + k0+qid];   al[mt][0] = ql[r0 + k0+qid];
                ah[mt][1] = qh[r1 + k0+qid];   al[mt][1] = ql[r1 + k0+qid];
                ah[mt][2] = qh[r0 + k0+qid+4]; al[mt][2] = ql[r0 + k0+qid+4];
                ah[mt][3] = qh[r1 + k0+qid+4]; al[mt][3] = ql[r1 + k0+qid+4];
            }
            #pragma unroll
            for (int nt = 0; nt < 4; nt++) {
                int kr = (nb + nt*8 + gid)*68;
                unsigned b0h = bhp[kr + k0+qid],   b0l = blp[kr + k0+qid];
                unsigned b1h = bhp[kr + k0+qid+4], b1l = blp[kr + k0+qid+4];
                #pragma unroll
                for (int mt = 0; mt < 2; mt++) {
                    mma_tf32(c[mt][nt], ah[mt][0],ah[mt][1],ah[mt][2],ah[mt][3], b0h, b1h);
                    mma_tf32(c[mt][nt], ah[mt][0],ah[mt][1],ah[mt][2],ah[mt][3], b0l, b1l);
                    mma_tf32(c[mt][nt], al[mt][0],al[mt][1],al[mt][2],al[mt][3], b0h, b1h);
                }
            }
        }
        #pragma unroll
        for (int mt = 0; mt < 2; mt++) {
            int r0 = mb + mt*16 + gid;
            int pq0 = posK[r0], pq1 = posK[r0+8];
            #pragma unroll
            for (int nt = 0; nt < 4; nt++) {
                int col = khh*64 + nb + nt*8 + qid*2;
                float is0 = invs[col]*0.125f, is1 = invs[col+1]*0.125f;
                int pk0 = posK[col], pk1 = posK[col+1];
                float s00 = c[mt][nt][0]*is0; if (pq0 == pk0) s00 = -5e4f;
                float s01 = c[mt][nt][1]*is1; if (pq0 == pk1) s01 = -5e4f;
                float s10 = c[mt][nt][2]*is0; if (pq1 == pk0) s10 = -5e4f;
                float s11 = c[mt][nt][3]*is1; if (pq1 == pk1) s11 = -5e4f;
                sd[r0*132 + col] = s00;     sd[r0*132 + col+1] = s01;
                sd[(r0+8)*132 + col] = s10; sd[(r0+8)*132 + col+1] = s11;
            }
        }
    }
    __syncthreads();

    {
        int r = tid >> 2, c4 = tid & 3;
        float vals[32];
        float mx = -1e30f;
        #pragma unroll
        for (int i = 0; i < 32; i++) { vals[i] = sd[r*132 + i*4 + c4]; mx = fmaxf(mx, vals[i]); }
        mx = fmaxf(mx, __shfl_xor_sync(0xffffffffu, mx, 1));
        mx = fmaxf(mx, __shfl_xor_sync(0xffffffffu, mx, 2));
        float se = 0.f;
        #pragma unroll
        for (int i = 0; i < 32; i++) { vals[i] = __expf(vals[i] - mx); se += vals[i]; }
        se += __shfl_xor_sync(0xffffffffu, se, 1);
        se += __shfl_xor_sync(0xffffffffu, se, 2);
        if (c4 == 0) slog[((size_t)bh*NHh + nh)*Tt + posK[r]] = mx + __logf(se);
        float inv_se = 1.f/se;
        #pragma unroll
        for (int i = 0; i < 32; i++) sd[r*132 + i*4 + c4] = vals[i]*inv_se;
    }
    __syncthreads();

    for (int i = tid; i < 64*16; i += 256) {
        int r = i >> 4, c4 = (i & 15)*4;
        float4 a = *(const float4*)&vg[(size_t)(b*Tt + posK[r])*Dd + h*DHh + c4];
        float av[4] = {a.x, a.y, a.z, a.w};
        float4 k2 = *(const float4*)&vg[(size_t)(b*Tt + posK[64+r])*Dd + h*DHh + c4];
        float kv[4] = {k2.x, k2.y, k2.z, k2.w};
        #pragma unroll
        for (int e = 0; e < 4; e++) {
            unsigned hA = f2tf32(av[e]);
            qh[r*68 + c4 + e] = hA;
            ql[r*68 + c4 + e] = f2tf32(av[e] - __uint_as_float(hA));
            unsigned hK = f2tf32(kv[e]);
            kh_[r*68 + c4 + e] = hK;
            kl_[r*68 + c4 + e] = f2tf32(kv[e] - __uint_as_float(hK));
        }
    }
    __syncthreads();

    {
        const int mb = (warp & 1)*32;
        const int db = ((warp >> 1) & 3)*16;
        float c[2][2][4];
        #pragma unroll
        for (int mt = 0; mt < 2; mt++)
            #pragma unroll
            for (int nt = 0; nt < 2; nt++)
                #pragma unroll
                for (int e = 0; e < 4; e++) c[mt][nt][e] = 0.f;

        #pragma unroll
        for (int kt = 0; kt < 16; kt++) {
            int k0 = kt*8;
            const unsigned* vh = (k0 < 64) ? qh : kh_;
            const unsigned* vl = (k0 < 64) ? ql : kl_;
            int kk = k0 & 63;
            unsigned ah[2][4], al[2][4];
            #pragma unroll
            for (int mt = 0; mt < 2; mt++) {
                int r0 = (mb + mt*16 + gid)*132;
                int r1 = r0 + 8*132;
                float x0 = sd[r0 + k0+qid];
                float x1 = sd[r1 + k0+qid];
                float x2 = sd[r0 + k0+qid+4];
                float x3 = sd[r1 + k0+qid+4];
                ah[mt][0] = f2tf32(x0); al[mt][0] = f2tf32(x0 - __uint_as_float(ah[mt][0]));
                ah[mt][1] = f2tf32(x1); al[mt][1] = f2tf32(x1 - __uint_as_float(ah[mt][1]));
                ah[mt][2] = f2tf32(x2); al[mt][2] = f2tf32(x2 - __uint_as_float(ah[mt][2]));
                ah[mt][3] = f2tf32(x3); al[mt][3] = f2tf32(x3 - __uint_as_float(ah[mt][3]));
            }
            #pragma unroll
            for (int nt = 0; nt < 2; nt++) {
                int d = db + nt*8 + gid;
                unsigned b0h = vh[(kk+qid)*68 + d],   b0l = vl[(kk+qid)*68 + d];
                unsigned b1h = vh[(kk+qid+4)*68 + d], b1l = vl[(kk+qid+4)*68 + d];
                #pragma unroll
                for (int mt = 0; mt < 2; mt++) {
                    mma_tf32(c[mt][nt], ah[mt][0],ah[mt][1],ah[mt][2],ah[mt][3], b0h, b1h);
                    mma_tf32(c[mt][nt], ah[mt][0],ah[mt][1],ah[mt][2],ah[mt][3], b0l, b1l);
                    mma_tf32(c[mt][nt], al[mt][0],al[mt][1],al[mt][2],al[mt][3], b0h, b1h);
                }
            }
        }
        size_t base0 = ((size_t)bh*NHh + nh)*Tt;
        #pragma unroll
        for (int mt = 0; mt < 2; mt++) {
            int r0 = mb + mt*16 + gid;
            float* bo0 = &bo[(base0 + posK[r0])*DHh];
            float* bo1 = &bo[(base0 + posK[r0+8])*DHh];
            #pragma unroll
            for (int nt = 0; nt < 2; nt++) {
                int col = db + nt*8 + qid*2;
                bo0[col] = c[mt][nt][0]; bo0[col+1] = c[mt][nt][1];
                bo1[col] = c[mt][nt][2]; bo1[col+1] = c[mt][nt][3];
            }
        }
    }
}

// ---------------- combine ----------------
__global__ void combine_kernel(const float* __restrict__ slog,
                               const float* __restrict__ bo,
                               float* __restrict__ ao) {
    int idx = blockIdx.x*256 + threadIdx.x;
    if (idx >= BHn*Tt*16) return;
    int d4 = (idx & 15)*4;
    int t  = (idx >> 4) & (Tt-1);
    int bh = idx >> 14;
    float lg[NHh];
    float mx = -1e30f;
    #pragma unroll
    for (int i = 0; i < NHh; i++) {
        lg[i] = slog[((size_t)bh*NHh + i)*Tt + t];
        mx = fmaxf(mx, lg[i]);
    }
    float se = 0.f;
    #pragma unroll
    for (int i = 0; i < NHh; i++) { lg[i] = __expf(lg[i] - mx); se += lg[i]; }
    float inv = 1.f/se;
    float4 out = make_float4(0.f, 0.f, 0.f, 0.f);
    #pragma unroll
    for (int i = 0; i < NHh; i++) {
        float w = lg[i]*inv;
        float4 bv = *(const float4*)&bo[(((size_t)bh*NHh + i)*Tt + t)*DHh + d4];
        out.x += w*bv.x; out.y += w*bv.y; out.z += w*bv.z; out.w += w*bv.w;
    }
    int b = bh >> 3, h = bh & 7;
    *(float4*)&ao[(size_t)(b*Tt + t)*Dd + h*DHh + d4] = out;
}

// ---------------- pooling + fc ----------------
__global__ void pool_kernel(const float* __restrict__ xn, float* __restrict__ pool) {
    int b = blockIdx.x, d = threadIdx.x;
    float s = 0.f;
    for (int t = 0; t < Tt; t++) s += xn[(size_t)(b*Tt + t)*Dd + d];
    pool[b*Dd + d] = s * (1.f/(float)Tt);
}

__global__ void fc_kernel(const float* __restrict__ pool,
                          const float* __restrict__ Wfc, float* __restrict__ out) {
    int b = blockIdx.x, n = threadIdx.x;
    float s = 0.f;
    for (int kk = 0; kk < Dd; kk++) s += pool[b*Dd + kk]*Wfc[kk*Dd + n];
    out[b*Dd + n] = s;
}

// ---------------- orchestration ----------------
extern "C" void kernel_launch(void* const* d_in, const int* in_sizes, int n_in,
                              void* d_out, int out_size) {
    const int*   ids = (const int*)  d_in[0];
    const float* tok = (const float*)d_in[1];
    const float* pos = (const float*)d_in[2];
    const float* lag = (const float*)d_in[3];
    const float* lab = (const float*)d_in[4];
    const float* Wqk = (const float*)d_in[5];
    const float* Wv  = (const float*)d_in[6];
    const float* Wo  = (const float*)d_in[7];
    const float* lfg = (const float*)d_in[8];
    const float* lfb = (const float*)d_in[9];
    const float* W1  = (const float*)d_in[10];
    const float* b1  = (const float*)d_in[11];
    const float* W2  = (const float*)d_in[12];
    const float* b2  = (const float*)d_in[13];
    const float* lng = (const float*)d_in[14];
    const float* lnb = (const float*)d_in[15];
    const float* Wfc = (const float*)d_in[16];
    const float* rot = (const float*)d_in[17];
    float* out = (float*)d_out;

    float *x1, *x2, *xn, *qk, *v, *ao, *ffh, *bo, *slog, *pool;
    int *st, *bkt;
    cudaGetSymbolAddress((void**)&x1,   g_x1);
    cudaGetSymbolAddress((void**)&x2,   g_x2);
    cudaGetSymbolAddress((void**)&xn,   g_xn);
    cudaGetSymbolAddress((void**)&qk,   g_qk);
    cudaGetSymbolAddress((void**)&v,    g_v);
    cudaGetSymbolAddress((void**)&ao,   g_ao);
    cudaGetSymbolAddress((void**)&ffh,  g_ffh);
    cudaGetSymbolAddress((void**)&bo,   g_bo);
    cudaGetSymbolAddress((void**)&slog, g_slog);
    cudaGetSymbolAddress((void**)&pool, g_pool);
    cudaGetSymbolAddress((void**)&st,   g_st);
    cudaGetSymbolAddress((void**)&bkt,  g_bkt);

    const int ATTN_SMEM = 4*64*68*4 + 64*132*4 + 128*4 + 128*4;   // 104448
    cudaFuncSetAttribute(attn_kernel, cudaFuncAttributeMaxDynamicSharedMemorySize, ATTN_SMEM);

    const int M = Bb*Tt;

    embed_kernel<<<(Bb*Tt*Dd + 255)/256, 256>>>(ids, tok, pos, x1, x2);

    for (int l = 0; l < DEPTHL; l++) {
        const float* Wqk_l = Wqk + (size_t)l*Dd*Dd;
        const float* Wv_l  = Wv  + (size_t)l*Dd*Dd;
        const float* Wo_l  = Wo  + (size_t)l*Dd*Dd;
        const float* W1_l  = W1  + (size_t)l*Dd*FFf;
        const float* W2_l  = W2  + (size_t)l*FFf*Dd;
        const float* b1_l  = b1  + (size_t)l*FFf;
        const float* b2_l  = b2  + (size_t)l*Dd;
        const float* rot_l = rot + (size_t)l*DHh*64;

        // attention block: x1 += attn(LN(x2)) @ Wo
        ln_kernel<<<M, 256>>>(x2, nullptr, xn, lag + l*Dd, lab + l*Dd);
        gemm_kernel<0><<<dim3(1024/128, M/128), 256>>>(xn, Wqk_l, nullptr, qk,
                                                       M, Dd, Wv_l, v, Dd, Dd);
        hash_kernel<<<BHn*16, 256>>>(rot_l, qk, bkt);
        sort_kernel<<<BHn*NHh, 512>>>(bkt, st);
        attn_kernel<<<dim3(NC, BHn), 256, ATTN_SMEM>>>(st, qk, v, slog, bo);
        combine_kernel<<<(BHn*Tt*16)/256, 256>>>(slog, bo, ao);
        gemm_kernel<3><<<dim3(Dd/128, M/128), 256>>>(ao, Wo_l, nullptr, x1,
                                                     M, Dd, nullptr, nullptr, 0, Dd);

        // feed-forward block: x2 += gelu(LN(x1)@W1 + b1) @ W2 + b2
        ln_kernel<<<M, 256>>>(x1, nullptr, xn, lfg + l*Dd, lfb + l*Dd);
        gemm_kernel<1><<<dim3(FFf/128, M/128), 256>>>(xn, W1_l, b1_l, ffh,
                                                      M, Dd, nullptr, nullptr, 0, FFf);
        gemm_kernel<4><<<dim3(Dd/128, M/128), 256>>>(ffh, W2_l, b2_l, x2,
                                                     M, FFf, nullptr, nullptr, 0, Dd);
    }

    // final: 0.5*(x1+x2) -> LN -> mean over T -> @ Wfc
    ln_kernel<<<M, 256>>>(x1, x2, xn, lng, lnb);
    pool_kernel<<<Bb, Dd>>>(xn, pool);
    fc_kernel<<<Bb, Dd>>>(pool, Wfc, out);
}

// round 15
// speedup vs baseline: 1.7455x; 1.0806x over previous
#include <cuda_runtime.h>
#include <math.h>
#include <stdint.h>

#define Bb 8
#define Tt 1024
#define Dd 512
#define Hh 8
#define DHh 64
#define DEPTHL 8
#define FFf 2048
#define NHh 8
#define BSz 64
#define NBk 16
#define NC (NHh*NBk)
#define BHn (Bb*Hh)
#define SEG (NHh*Tt)

#define PIT 36   // packed-pair row pitch (words)

// ---------------- scratch ----------------
__device__ float g_x1[Bb*Tt*Dd];
__device__ float g_x2[Bb*Tt*Dd];
__device__ float g_xn[Bb*Tt*Dd];
__device__ float g_qk[Bb*Tt*Dd];
__device__ float g_v [Bb*Tt*Dd];
__device__ float g_ao[Bb*Tt*Dd];
__device__ float g_ffh[Bb*Tt*FFf];
__device__ float g_bo[(size_t)BHn*NHh*Tt*DHh];
__device__ float g_slog[BHn*NHh*Tt];
__device__ int   g_st [BHn*SEG];
__device__ int   g_bkt[BHn*SEG];
__device__ float g_pool[Bb*Dd];

// ---------------- helpers ----------------
__device__ __forceinline__ float gelu_fast(float x) {
    float u = 0.7978845608028654f*(x + 0.044715f*x*x*x);
    float t = 1.f - 2.f/(__expf(2.f*u) + 1.f);
    return 0.5f*x*(1.f + t);
}

__device__ __forceinline__ float blockReduceSum256(float val, float* red) {
    #pragma unroll
    for (int o = 16; o; o >>= 1) val += __shfl_xor_sync(0xffffffffu, val, o);
    int w = threadIdx.x >> 5;
    if ((threadIdx.x & 31) == 0) red[w] = val;
    __syncthreads();
    float r = (threadIdx.x < 8) ? red[threadIdx.x] : 0.f;
    if (threadIdx.x < 32) {
        #pragma unroll
        for (int o = 4; o; o >>= 1) r += __shfl_xor_sync(0xffffffffu, r, o);
        if (threadIdx.x == 0) red[0] = r;
    }
    __syncthreads();
    float out = red[0];
    __syncthreads();
    return out;
}

__device__ __forceinline__ void mma_bf16(float* c,
    unsigned a0, unsigned a1, unsigned a2, unsigned a3,
    unsigned b0, unsigned b1) {
    asm volatile(
        "mma.sync.aligned.m16n8k16.row.col.f32.bf16.bf16.f32 "
        "{%0,%1,%2,%3}, {%4,%5,%6,%7}, {%8,%9}, {%0,%1,%2,%3};"
        : "+f"(c[0]), "+f"(c[1]), "+f"(c[2]), "+f"(c[3])
        : "r"(a0), "r"(a1), "r"(a2), "r"(a3), "r"(b0), "r"(b1));
}

// split (x0,x1) pair into packed bf16x2 hi and lo (residual) words; x0 in low half.
__device__ __forceinline__ void split_pair(float x0, float x1,
                                           unsigned &hi, unsigned &lo) {
    unsigned h;
    asm("cvt.rn.bf16x2.f32 %0, %1, %2;" : "=r"(h) : "f"(x1), "f"(x0));
    float h0 = __uint_as_float(h << 16);
    float h1 = __uint_as_float(h & 0xffff0000u);
    float l0 = x0 - h0, l1 = x1 - h1;
    asm("cvt.rn.bf16x2.f32 %0, %1, %2;" : "=r"(lo) : "f"(l1), "f"(l0));
    hi = h;
}

__device__ __forceinline__ void cp16(void* smem, const void* gmem) {
    unsigned s = (unsigned)__cvta_generic_to_shared(smem);
    asm volatile("cp.async.ca.shared.global [%0], [%1], 16;" :: "r"(s), "l"(gmem));
}

// ---------------- embedding ----------------
__global__ void embed_kernel(const int* __restrict__ ids,
                             const float* __restrict__ tok,
                             const float* __restrict__ pos,
                             float* __restrict__ x1, float* __restrict__ x2) {
    int i = blockIdx.x*256 + threadIdx.x;
    if (i >= Bb*Tt*Dd) return;
    int d = i & (Dd-1);
    int bt = i >> 9;
    int t = bt & (Tt-1);
    int id = ids[bt];
    if (id < 0) id = 0;
    if (id >= 6400) id = 6399;
    float v = tok[(size_t)id*Dd + d] + pos[t*Dd + d];
    x1[i] = v; x2[i] = v;
}

// ---------------- layernorm ----------------
__global__ void ln_kernel(const float* __restrict__ x, const float* __restrict__ xb,
                          float* __restrict__ y,
                          const float* __restrict__ g, const float* __restrict__ bia) {
    __shared__ float red[8];
    int row = blockIdx.x;
    int i0 = row*Dd + threadIdx.x;
    float v0, v1;
    if (xb) { v0 = 0.5f*(x[i0] + xb[i0]); v1 = 0.5f*(x[i0+256] + xb[i0+256]); }
    else    { v0 = x[i0];                 v1 = x[i0+256]; }
    float s = blockReduceSum256(v0+v1, red);
    float mean = s * (1.f/512.f);
    float d0 = v0 - mean, d1 = v1 - mean;
    float s2 = blockReduceSum256(d0*d0 + d1*d1, red);
    float inv = rsqrtf(s2*(1.f/512.f) + 1e-5f);
    y[i0]     = d0*inv*g[threadIdx.x]     + bia[threadIdx.x];
    y[i0+256] = d1*inv*g[threadIdx.x+256] + bia[threadIdx.x+256];
}

// ---------------- tensor-core GEMM (3-term bf16 k16, cp.async double-buffered) ----------------
template<int EPI>
__global__ void __launch_bounds__(256) gemm_kernel(const float* __restrict__ A,
                            const float* __restrict__ Bm,
                            const float* __restrict__ bias, float* __restrict__ C,
                            int M, int K,
                            const float* __restrict__ Bm2, float* __restrict__ C2,
                            int nHalf, int Nplain) {
    __shared__ float As[2][128][20];
    __shared__ float Bs[2][16][132];

    const int tid  = threadIdx.x;
    const int lane = tid & 31;
    const int warp = tid >> 5;
    const int wm = warp & 1;
    const int wn = warp >> 1;
    const int gid = lane >> 2;
    const int qid = lane & 3;
    const int bm = blockIdx.y*128;

    const float* Bu = Bm;
    float* Cu = C;
    int bn = blockIdx.x*128;
    int Nld = Nplain;
    if (Bm2 != nullptr) {
        Nld = nHalf;
        if (bn >= nHalf) { Bu = Bm2; Cu = C2; bn -= nHalf; }
    }

    float c[4][4][4];
    #pragma unroll
    for (int mt = 0; mt < 4; mt++)
        #pragma unroll
        for (int nt = 0; nt < 4; nt++)
            #pragma unroll
            for (int e = 0; e < 4; e++) c[mt][nt][e] = 0.f;

    const int aM  = (tid + 0)   >> 2, aO  = ((tid + 0)   & 3)*4;
    const int aM2 = (tid + 256) >> 2, aO2 = ((tid + 256) & 3)*4;
    const int bKk  = (tid + 0)   >> 5, bNo  = ((tid + 0)   & 31)*4;
    const int bKk2 = (tid + 256) >> 5, bNo2 = ((tid + 256) & 31)*4;

    const int nk = K >> 4;

    {
        cp16(&As[0][aM ][aO ], A + (size_t)(bm + aM )*K + aO );
        cp16(&As[0][aM2][aO2], A + (size_t)(bm + aM2)*K + aO2);
        cp16(&Bs[0][bKk ][bNo ], Bu + (size_t)bKk *Nld + bn + bNo );
        cp16(&Bs[0][bKk2][bNo2], Bu + (size_t)bKk2*Nld + bn + bNo2);
        asm volatile("cp.async.commit_group;");
        asm volatile("cp.async.wait_group 0;");
    }
    __syncthreads();

    for (int kt = 0; kt < nk; kt++) {
        const int cur = kt & 1;
        if (kt + 1 < nk) {
            const int nxt = cur ^ 1;
            int k0 = (kt + 1)*16;
            cp16(&As[nxt][aM ][aO ], A + (size_t)(bm + aM )*K + k0 + aO );
            cp16(&As[nxt][aM2][aO2], A + (size_t)(bm + aM2)*K + k0 + aO2);
            cp16(&Bs[nxt][bKk ][bNo ], Bu + (size_t)(k0 + bKk )*Nld + bn + bNo );
            cp16(&Bs[nxt][bKk2][bNo2], Bu + (size_t)(k0 + bKk2)*Nld + bn + bNo2);
            asm volatile("cp.async.commit_group;");
        }

        unsigned ah[4][4], al[4][4];
        #pragma unroll
        for (int mt = 0; mt < 4; mt++) {
            int r0 = wm*64 + mt*16 + gid;
            float2 p0 = *(const float2*)&As[cur][r0  ][2*qid];
            float2 p1 = *(const float2*)&As[cur][r0+8][2*qid];
            float2 p2 = *(const float2*)&As[cur][r0  ][2*qid+8];
            float2 p3 = *(const float2*)&As[cur][r0+8][2*qid+8];
            split_pair(p0.x, p0.y, ah[mt][0], al[mt][0]);
            split_pair(p1.x, p1.y, ah[mt][1], al[mt][1]);
            split_pair(p2.x, p2.y, ah[mt][2], al[mt][2]);
            split_pair(p3.x, p3.y, ah[mt][3], al[mt][3]);
        }
        #pragma unroll
        for (int nt = 0; nt < 4; nt++) {
            int nc = wn*32 + nt*8 + gid;
            unsigned b0h, b0l, b1h, b1l;
            split_pair(Bs[cur][2*qid  ][nc], Bs[cur][2*qid+1][nc], b0h, b0l);
            split_pair(Bs[cur][2*qid+8][nc], Bs[cur][2*qid+9][nc], b1h, b1l);
            #pragma unroll
            for (int mt = 0; mt < 4; mt++) {
                mma_bf16(c[mt][nt], ah[mt][0],ah[mt][1],ah[mt][2],ah[mt][3], b0h, b1h);
                mma_bf16(c[mt][nt], ah[mt][0],ah[mt][1],ah[mt][2],ah[mt][3], b0l, b1l);
                mma_bf16(c[mt][nt], al[mt][0],al[mt][1],al[mt][2],al[mt][3], b0h, b1h);
            }
        }
        asm volatile("cp.async.wait_group 0;");
        __syncthreads();
    }

    #pragma unroll
    for (int mt = 0; mt < 4; mt++) {
        #pragma unroll
        for (int nt = 0; nt < 4; nt++) {
            int row = bm + wm*64 + mt*16 + gid;
            int col = bn + wn*32 + nt*8 + qid*2;
            float* p0 = Cu + (size_t)row*Nld + col;
            float* p1 = Cu + (size_t)(row+8)*Nld + col;
            float v00 = c[mt][nt][0], v01 = c[mt][nt][1];
            float v10 = c[mt][nt][2], v11 = c[mt][nt][3];
            if (EPI == 0) {
                p0[0] = v00; p0[1] = v01; p1[0] = v10; p1[1] = v11;
            } else if (EPI == 1) {
                float b0v = bias[col], b1v = bias[col+1];
                p0[0] = gelu_fast(v00 + b0v); p0[1] = gelu_fast(v01 + b1v);
                p1[0] = gelu_fast(v10 + b0v); p1[1] = gelu_fast(v11 + b1v);
            } else if (EPI == 3) {
                p0[0] += v00; p0[1] += v01; p1[0] += v10; p1[1] += v11;
            } else {
                float b0v = bias[col], b1v = bias[col+1];
                p0[0] += v00 + b0v; p0[1] += v01 + b1v;
                p1[0] += v10 + b0v; p1[1] += v11 + b1v;
            }
        }
    }
}

// ---------------- LSH hashing: 2 tokens/thread, shared rot reads ----------------
__global__ void hash_kernel(const float* __restrict__ rot,
                            const float* __restrict__ qk, int* __restrict__ bkt) {
    __shared__ float rs[64*64];
    __shared__ float sq[64][68];
    int blk = blockIdx.x;
    int bh = blk >> 4;
    int t0 = (blk & 15)*64;
    int b = bh >> 3, h = bh & 7;
    int tid = threadIdx.x;
    for (int i = tid; i < 64*64; i += 256) rs[i] = rot[i];
    for (int i = tid; i < 64*16; i += 256) {
        int r = i >> 4, c4 = (i & 15)*4;
        float4 q4 = *(const float4*)&qk[(size_t)(b*Tt + t0 + r)*Dd + h*DHh + c4];
        sq[r][c4+0] = q4.x; sq[r][c4+1] = q4.y; sq[r][c4+2] = q4.z; sq[r][c4+3] = q4.w;
    }
    __syncthreads();
    int tl = tid >> 3;            // 0..31 (handles tl and tl+32)
    int nh = tid & 7;
    float rv[8], rw[8];
    #pragma unroll
    for (int r = 0; r < 8; r++) { rv[r] = 0.f; rw[r] = 0.f; }
    #pragma unroll 4
    for (int d = 0; d < 64; d++) {
        float q1 = sq[tl][d];
        float q2 = sq[tl+32][d];
        float4 r0 = *(const float4*)&rs[d*64 + nh*8];
        float4 r1 = *(const float4*)&rs[d*64 + nh*8 + 4];
        rv[0] += q1*r0.x; rv[1] += q1*r0.y; rv[2] += q1*r0.z; rv[3] += q1*r0.w;
        rv[4] += q1*r1.x; rv[5] += q1*r1.y; rv[6] += q1*r1.z; rv[7] += q1*r1.w;
        rw[0] += q2*r0.x; rw[1] += q2*r0.y; rw[2] += q2*r0.z; rw[3] += q2*r0.w;
        rw[4] += q2*r1.x; rw[5] += q2*r1.y; rw[6] += q2*r1.z; rw[7] += q2*r1.w;
    }
    {
        int best = 0; float bv = rv[0];
        #pragma unroll
        for (int r = 1; r < 8; r++) if (rv[r] > bv) { bv = rv[r]; best = r; }
        #pragma unroll
        for (int r = 0; r < 8; r++) { float nv = -rv[r]; if (nv > bv) { bv = nv; best = 8 + r; } }
        bkt[(bh*NHh + nh)*Tt + t0 + tl] = best;
    }
    {
        int best = 0; float bv = rw[0];
        #pragma unroll
        for (int r = 1; r < 8; r++) if (rw[r] > bv) { bv = rw[r]; best = r; }
        #pragma unroll
        for (int r = 0; r < 8; r++) { float nv = -rw[r]; if (nv > bv) { bv = nv; best = 8 + r; } }
        bkt[(bh*NHh + nh)*Tt + t0 + tl + 32] = best;
    }
}

// ---------------- stable counting sort ----------------
__global__ void sort_kernel(const int* __restrict__ bkt, int* __restrict__ st) {
    __shared__ int sb[Tt];
    __shared__ int cnt[16];
    __shared__ int off[16];
    int base = blockIdx.x*Tt;
    int tid = threadIdx.x;
    for (int i = tid; i < Tt; i += 512) sb[i] = bkt[base + i];
    __syncthreads();
    int w = tid >> 5, lane = tid & 31;
    int c = 0;
    for (int it = 0; it < 32; it++) {
        unsigned m = __ballot_sync(0xffffffffu, sb[it*32 + lane] == w);
        c += __popc(m);
    }
    if (lane == 0) cnt[w] = c;
    __syncthreads();
    if (tid == 0) {
        int s = 0;
        for (int i = 0; i < 16; i++) { off[i] = s; s += cnt[i]; }
    }
    __syncthreads();
    int p = off[w];
    for (int it = 0; it < 32; it++) {
        int t = it*32 + lane;
        int bb = sb[t];
        unsigned m = __ballot_sync(0xffffffffu, bb == w);
        if (bb == w) {
            int pos = p + __popc(m & ((1u << lane) - 1u));
            st[base + pos] = t;
        }
        p += __popc(m);
    }
}

// ---------------- chunked LSH attention (3-term bf16 k16, packed-pair tiles) ----------------
__global__ void __launch_bounds__(256,2) attn_kernel(const int* __restrict__ st,
                                                   const float* __restrict__ qk,
                                                   const float* __restrict__ vg,
                                                   float* __restrict__ slog,
                                                   float* __restrict__ bo) {
    extern __shared__ float sm[];
    unsigned* qh = (unsigned*)sm;          // [64*PIT] packed hi (q / V-half0 d-rows)
    unsigned* ql = qh + 64*PIT;
    unsigned* kh = ql + 64*PIT;            // K half1 / V-half1
    unsigned* kl = kh + 64*PIT;
    float* sd   = (float*)(kl + 64*PIT);   // [64*132] dots -> probs
    float* invs = sd + 64*132;             // [128]
    int*   posK = (int*)(invs + 128);      // [128]

    int n = blockIdx.x, bh = blockIdx.y;
    int b = bh >> 3, h = bh & 7;
    int tid = threadIdx.x;
    int nh = n >> 4;
    int segb = bh*SEG;

    const int lane = tid & 31, warp = tid >> 5;
    const int gid = lane >> 2, qid = lane & 3;

    if (tid < 128) {
        int cc = (tid < 64) ? n : ((n + NC - 1) & (NC-1));
        posK[tid] = st[segb + cc*BSz + (tid & 63)];
    }
    __syncthreads();

    // load q tile (keys half0) and K half1; pack adjacent-d pairs, split hi/lo
    for (int i = tid; i < 64*16; i += 256) {
        int r = i >> 4, c4 = (i & 15)*4;
        int wp = c4 >> 1;                 // word index (2 words per 4 floats)
        float4 a = *(const float4*)&qk[(size_t)(b*Tt + posK[r])*Dd + h*DHh + c4];
        unsigned h0, l0, h1, l1;
        split_pair(a.x, a.y, h0, l0); split_pair(a.z, a.w, h1, l1);
        qh[r*PIT + wp] = h0; qh[r*PIT + wp+1] = h1;
        ql[r*PIT + wp] = l0; ql[r*PIT + wp+1] = l1;
        float4 k2 = *(const float4*)&qk[(size_t)(b*Tt + posK[64+r])*Dd + h*DHh + c4];
        split_pair(k2.x, k2.y, h0, l0); split_pair(k2.z, k2.w, h1, l1);
        kh[r*PIT + wp] = h0; kh[r*PIT + wp+1] = h1;
        kl[r*PIT + wp] = l0; kl[r*PIT + wp+1] = l1;
    }
    __syncthreads();

    // key inverse norms from reconstructed hi+lo
    if (tid < 128) {
        const unsigned* ph = (tid < 64) ? qh : kh;
        const unsigned* pl = (tid < 64) ? ql : kl;
        int r = tid & 63;
        float s = 0.f;
        #pragma unroll 8
        for (int w = 0; w < 32; w++) {
            unsigned hw = ph[r*PIT + w], lw = pl[r*PIT + w];
            float x0 = __uint_as_float(hw << 16) + __uint_as_float(lw << 16);
            float x1 = __uint_as_float(hw & 0xffff0000u) + __uint_as_float(lw & 0xffff0000u);
            s += x0*x0 + x1*x1;
        }
        invs[tid] = 1.f/(sqrtf(s) + 1e-8f);
    }
    __syncthreads();

    // ---- QK^T: warp = (mpair, key-half, n-group), k16 steps over d ----
    {
        const int mb  = (warp & 1)*32;
        const int khh = (warp >> 1) & 1;
        const int nb  = (warp >> 2)*32;
        const unsigned* bhp = khh ? kh : qh;
        const unsigned* blp = khh ? kl : ql;
        float c[2][4][4];
        #pragma unroll
        for (int mt = 0; mt < 2; mt++)
            #pragma unroll
            for (int nt = 0; nt < 4; nt++)
                #pragma unroll
                for (int e = 0; e < 4; e++) c[mt][nt][e] = 0.f;

        #pragma unroll
        for (int kt = 0; kt < 4; kt++) {
            int kw = kt*8;
            unsigned ah[2][4], al[2][4];
            #pragma unroll
            for (int mt = 0; mt < 2; mt++) {
                int r0 = (mb + mt*16 + gid)*PIT;
                int r1 = r0 + 8*PIT;
                ah[mt][0] = qh[r0 + kw+qid];   al[mt][0] = ql[r0 + kw+qid];
                ah[mt][1] = qh[r1 + kw+qid];   al[mt][1] = ql[r1 + kw+qid];
                ah[mt][2] = qh[r0 + kw+qid+4]; al[mt][2] = ql[r0 + kw+qid+4];
                ah[mt][3] = qh[r1 + kw+qid+4]; al[mt][3] = ql[r1 + kw+qid+4];
            }
            #pragma unroll
            for (int nt = 0; nt < 4; nt++) {
                int kr = (nb + nt*8 + gid)*PIT;
                unsigned b0h = bhp[kr + kw+qid],   b0l = blp[kr + kw+qid];
                unsigned b1h = bhp[kr + kw+qid+4], b1l = blp[kr + kw+qid+4];
                #pragma unroll
                for (int mt = 0; mt < 2; mt++) {
                    mma_bf16(c[mt][nt], ah[mt][0],ah[mt][1],ah[mt][2],ah[mt][3], b0h, b1h);
                    mma_bf16(c[mt][nt], ah[mt][0],ah[mt][1],ah[mt][2],ah[mt][3], b0l, b1l);
                    mma_bf16(c[mt][nt], al[mt][0],al[mt][1],al[mt][2],al[mt][3], b0h, b1h);
                }
            }
        }
        #pragma unroll
        for (int mt = 0; mt < 2; mt++) {
            int r0 = mb + mt*16 + gid;
            int pq0 = posK[r0], pq1 = posK[r0+8];
            #pragma unroll
            for (int nt = 0; nt < 4; nt++) {
                int col = khh*64 + nb + nt*8 + qid*2;
                float is0 = invs[col]*0.125f, is1 = invs[col+1]*0.125f;
                int pk0 = posK[col], pk1 = posK[col+1];
                float s00 = c[mt][nt][0]*is0; if (pq0 == pk0) s00 = -5e4f;
                float s01 = c[mt][nt][1]*is1; if (pq0 == pk1) s01 = -5e4f;
                float s10 = c[mt][nt][2]*is0; if (pq1 == pk0) s10 = -5e4f;
                float s11 = c[mt][nt][3]*is1; if (pq1 == pk1) s11 = -5e4f;
                sd[r0*132 + col] = s00;     sd[r0*132 + col+1] = s01;
                sd[(r0+8)*132 + col] = s10; sd[(r0+8)*132 + col+1] = s11;
            }
        }
    }
    __syncthreads();

    // ---- softmax per row ----
    {
        int r = tid >> 2, c4 = tid & 3;
        float vals[32];
        float mx = -1e30f;
        #pragma unroll
        for (int i = 0; i < 32; i++) { vals[i] = sd[r*132 + i*4 + c4]; mx = fmaxf(mx, vals[i]); }
        mx = fmaxf(mx, __shfl_xor_sync(0xffffffffu, mx, 1));
        mx = fmaxf(mx, __shfl_xor_sync(0xffffffffu, mx, 2));
        float se = 0.f;
        #pragma unroll
        for (int i = 0; i < 32; i++) { vals[i] = __expf(vals[i] - mx); se += vals[i]; }
        se += __shfl_xor_sync(0xffffffffu, se, 1);
        se += __shfl_xor_sync(0xffffffffu, se, 2);
        if (c4 == 0) slog[((size_t)bh*NHh + nh)*Tt + posK[r]] = mx + __logf(se);
        float inv_se = 1.f/se;
        #pragma unroll
        for (int i = 0; i < 32; i++) sd[r*132 + i*4 + c4] = vals[i]*inv_se;
    }
    __syncthreads();

    // ---- load V halves, k-packed (transposed pairs): vh[d*PIT + kpair] ----
    // i covers (half, kpair 0..31, d4 0..15): loads key rows 2p, 2p+1 at 4 d's
    for (int i = tid; i < 1024; i += 256) {
        int half = i >> 9;
        int p  = (i >> 4) & 31;
        int d4 = (i & 15)*4;
        unsigned* vh = half ? kh : qh;
        unsigned* vl = half ? kl : ql;
        float4 a0 = *(const float4*)&vg[(size_t)(b*Tt + posK[half*64 + 2*p  ])*Dd + h*DHh + d4];
        float4 a1 = *(const float4*)&vg[(size_t)(b*Tt + posK[half*64 + 2*p+1])*Dd + h*DHh + d4];
        unsigned hw, lw;
        split_pair(a0.x, a1.x, hw, lw); vh[(d4+0)*PIT + p] = hw; vl[(d4+0)*PIT + p] = lw;
        split_pair(a0.y, a1.y, hw, lw); vh[(d4+1)*PIT + p] = hw; vl[(d4+1)*PIT + p] = lw;
        split_pair(a0.z, a1.z, hw, lw); vh[(d4+2)*PIT + p] = hw; vl[(d4+2)*PIT + p] = lw;
        split_pair(a0.w, a1.w, hw, lw); vh[(d4+3)*PIT + p] = hw; vl[(d4+3)*PIT + p] = lw;
    }
    __syncthreads();

    // ---- PV: warp = (mpair, d-group), k16 steps over 128 keys ----
    {
        const int mb = (warp & 1)*32;
        const int db = ((warp >> 1) & 3)*16;
        float c[2][2][4];
        #pragma unroll
        for (int mt = 0; mt < 2; mt++)
            #pragma unroll
            for (int nt = 0; nt < 2; nt++)
                #pragma unroll
                for (int e = 0; e < 4; e++) c[mt][nt][e] = 0.f;

        #pragma unroll
        for (int kt = 0; kt < 8; kt++) {
            int k0 = kt*16;
            const unsigned* vh = (kt < 4) ? qh : kh;
            const unsigned* vl = (kt < 4) ? ql : kl;
            int kw = (kt & 3)*8;
            unsigned ah[2][4], al[2][4];
            #pragma unroll
            for (int mt = 0; mt < 2; mt++) {
                int r0 = (mb + mt*16 + gid)*132;
                int r1 = r0 + 8*132;
                split_pair(sd[r0 + k0+2*qid],   sd[r0 + k0+2*qid+1],   ah[mt][0], al[mt][0]);
                split_pair(sd[r1 + k0+2*qid],   sd[r1 + k0+2*qid+1],   ah[mt][1], al[mt][1]);
                split_pair(sd[r0 + k0+2*qid+8], sd[r0 + k0+2*qid+9],   ah[mt][2], al[mt][2]);
                split_pair(sd[r1 + k0+2*qid+8], sd[r1 + k0+2*qid+9],   ah[mt][3], al[mt][3]);
            }
            #pragma unroll
            for (int nt = 0; nt < 2; nt++) {
                int d = db + nt*8 + gid;
                unsigned b0h = vh[d*PIT + kw + qid],   b0l = vl[d*PIT + kw + qid];
                unsigned b1h = vh[d*PIT + kw + qid+4], b1l = vl[d*PIT + kw + qid+4];
                #pragma unroll
                for (int mt = 0; mt < 2; mt++) {
                    mma_bf16(c[mt][nt], ah[mt][0],ah[mt][1],ah[mt][2],ah[mt][3], b0h, b1h);
                    mma_bf16(c[mt][nt], ah[mt][0],ah[mt][1],ah[mt][2],ah[mt][3], b0l, b1l);
                    mma_bf16(c[mt][nt], al[mt][0],al[mt][1],al[mt][2],al[mt][3], b0h, b1h);
                }
            }
        }
        size_t base0 = ((size_t)bh*NHh + nh)*Tt;
        #pragma unroll
        for (int mt = 0; mt < 2; mt++) {
            int r0 = mb + mt*16 + gid;
            float* bo0 = &bo[(base0 + posK[r0])*DHh];
            float* bo1 = &bo[(base0 + posK[r0+8])*DHh];
            #pragma unroll
            for (int nt = 0; nt < 2; nt++) {
                int col = db + nt*8 + qid*2;
                bo0[col] = c[mt][nt][0]; bo0[col+1] = c[mt][nt][1];
                bo1[col] = c[mt][nt][2]; bo1[col+1] = c[mt][nt][3];
            }
        }
    }
}

// ---------------- combine ----------------
__global__ void combine_kernel(const float* __restrict__ slog,
                               const float* __restrict__ bo,
                               float* __restrict__ ao) {
    int idx = blockIdx.x*256 + threadIdx.x;
    if (idx >= BHn*Tt*16) return;
    int d4 = (idx & 15)*4;
    int t  = (idx >> 4) & (Tt-1);
    int bh = idx >> 14;
    float lg[NHh];
    float mx = -1e30f;
    #pragma unroll
    for (int i = 0; i < NHh; i++) {
        lg[i] = slog[((size_t)bh*NHh + i)*Tt + t];
        mx = fmaxf(mx, lg[i]);
    }
    float se = 0.f;
    #pragma unroll
    for (int i = 0; i < NHh; i++) { lg[i] = __expf(lg[i] - mx); se += lg[i]; }
    float inv = 1.f/se;
    float4 out = make_float4(0.f, 0.f, 0.f, 0.f);
    #pragma unroll
    for (int i = 0; i < NHh; i++) {
        float w = lg[i]*inv;
        float4 bv = *(const float4*)&bo[(((size_t)bh*NHh + i)*Tt + t)*DHh + d4];
        out.x += w*bv.x; out.y += w*bv.y; out.z += w*bv.z; out.w += w*bv.w;
    }
    int b = bh >> 3, h = bh & 7;
    *(float4*)&ao[(size_t)(b*Tt + t)*Dd + h*DHh + d4] = out;
}

// ---------------- pooling + fc ----------------
__global__ void pool_kernel(const float* __restrict__ xn, float* __restrict__ pool) {
    int b = blockIdx.x, d = threadIdx.x;
    float s = 0.f;
    for (int t = 0; t < Tt; t++) s += xn[(size_t)(b*Tt + t)*Dd + d];
    pool[b*Dd + d] = s * (1.f/(float)Tt);
}

__global__ void fc_kernel(const float* __restrict__ pool,
                          const float* __restrict__ Wfc, float* __restrict__ out) {
    int b = blockIdx.x, n = threadIdx.x;
    float s = 0.f;
    for (int kk = 0; kk < Dd; kk++) s += pool[b*Dd + kk]*Wfc[kk*Dd + n];
    out[b*Dd + n] = s;
}

// ---------------- orchestration ----------------
extern "C" void kernel_launch(void* const* d_in, const int* in_sizes, int n_in,
                              void* d_out, int out_size) {
    const int*   ids = (const int*)  d_in[0];
    const float* tok = (const float*)d_in[1];
    const float* pos = (const float*)d_in[2];
    const float* lag = (const float*)d_in[3];
    const float* lab = (const float*)d_in[4];
    const float* Wqk = (const float*)d_in[5];
    const float* Wv  = (const float*)d_in[6];
    const float* Wo  = (const float*)d_in[7];
    const float* lfg = (const float*)d_in[8];
    const float* lfb = (const float*)d_in[9];
    const float* W1  = (const float*)d_in[10];
    const float* b1  = (const float*)d_in[11];
    const float* W2  = (const float*)d_in[12];
    const float* b2  = (const float*)d_in[13];
    const float* lng = (const float*)d_in[14];
    const float* lnb = (const float*)d_in[15];
    const float* Wfc = (const float*)d_in[16];
    const float* rot = (const float*)d_in[17];
    float* out = (float*)d_out;

    float *x1, *x2, *xn, *qk, *v, *ao, *ffh, *bo, *slog, *pool;
    int *st, *bkt;
    cudaGetSymbolAddress((void**)&x1,   g_x1);
    cudaGetSymbolAddress((void**)&x2,   g_x2);
    cudaGetSymbolAddress((void**)&xn,   g_xn);
    cudaGetSymbolAddress((void**)&qk,   g_qk);
    cudaGetSymbolAddress((void**)&v,    g_v);
    cudaGetSymbolAddress((void**)&ao,   g_ao);
    cudaGetSymbolAddress((void**)&ffh,  g_ffh);
    cudaGetSymbolAddress((void**)&bo,   g_bo);
    cudaGetSymbolAddress((void**)&slog, g_slog);
    cudaGetSymbolAddress((void**)&pool, g_pool);
    cudaGetSymbolAddress((void**)&st,   g_st);
    cudaGetSymbolAddress((void**)&bkt,  g_bkt);

    const int ATTN_SMEM = 4*64*PIT*4 + 64*132*4 + 128*4 + 128*4;   // 71680
    cudaFuncSetAttribute(attn_kernel, cudaFuncAttributeMaxDynamicSharedMemorySize, ATTN_SMEM);

    const int M = Bb*Tt;

    embed_kernel<<<(Bb*Tt*Dd + 255)/256, 256>>>(ids, tok, pos, x1, x2);

    for (int l = 0; l < DEPTHL; l++) {
        const float* Wqk_l = Wqk + (size_t)l*Dd*Dd;
        const float* Wv_l  = Wv  + (size_t)l*Dd*Dd;
        const float* Wo_l  = Wo  + (size_t)l*Dd*Dd;
        const float* W1_l  = W1  + (size_t)l*Dd*FFf;
        const float* W2_l  = W2  + (size_t)l*FFf*Dd;
        const float* b1_l  = b1  + (size_t)l*FFf;
        const float* b2_l  = b2  + (size_t)l*Dd;
        const float* rot_l = rot + (size_t)l*DHh*64;

        // attention block: x1 += attn(LN(x2)) @ Wo
        ln_kernel<<<M, 256>>>(x2, nullptr, xn, lag + l*Dd, lab + l*Dd);
        gemm_kernel<0><<<dim3(1024/128, M/128), 256>>>(xn, Wqk_l, nullptr, qk,
                                                       M, Dd, Wv_l, v, Dd, Dd);
        hash_kernel<<<BHn*16, 256>>>(rot_l, qk, bkt);
        sort_kernel<<<BHn*NHh, 512>>>(bkt, st);
        attn_kernel<<<dim3(NC, BHn), 256, ATTN_SMEM>>>(st, qk, v, slog, bo);
        combine_kernel<<<(BHn*Tt*16)/256, 256>>>(slog, bo, ao);
        gemm_kernel<3><<<dim3(Dd/128, M/128), 256>>>(ao, Wo_l, nullptr, x1,
                                                     M, Dd, nullptr, nullptr, 0, Dd);

        // feed-forward block: x2 += gelu(LN(x1)@W1 + b1) @ W2 + b2
        ln_kernel<<<M, 256>>>(x1, nullptr, xn, lfg + l*Dd, lfb + l*Dd);
        gemm_kernel<1><<<dim3(FFf/128, M/128), 256>>>(xn, W1_l, b1_l, ffh,
                                                      M, Dd, nullptr, nullptr, 0, FFf);
        gemm_kernel<4><<<dim3(Dd/128, M/128), 256>>>(ffh, W2_l, b2_l, x2,
                                                     M, FFf, nullptr, nullptr, 0, Dd);
    }

    // final: 0.5*(x1+x2) -> LN -> mean over T -> @ Wfc
    ln_kernel<<<M, 256>>>(x1, x2, xn, lng, lnb);
    pool_kernel<<<Bb, Dd>>>(xn, pool);
    fc_kernel<<<Bb, Dd>>>(pool, Wfc, out);
}